// round 2
// baseline (speedup 1.0000x reference)
#include <cuda_runtime.h>
#include <math.h>

#define Bn 4
#define Sn 2048
#define Dn 1024
#define Hn 16
#define DKn 64
#define Mn (Bn*Sn)   /* 8192 */
#define LD 68        /* smem row stride for attention tiles (float4-aligned, conflict-light) */

// Scratch (device globals: allocation-free per harness rules)
__device__ float g_Q[Bn*Hn*Sn*DKn];
__device__ float g_K[Bn*Hn*Sn*DKn];
__device__ float g_V[Bn*Hn*Sn*DKn];
__device__ float g_ctx[Mn*Dn];

// ---------------------------------------------------------------------------
// Tiled SGEMM: C[M,N] = A[M,K] @ W[K,N] + bias,  M=8192, N=K=1024.
// BM=BN=128, BK=8, 256 threads, 8x8 per thread.
// dst: 0/1/2 -> write g_Q/g_K/g_V in head-split (B,H,S,DK) layout
//      3     -> A = g_ctx, plain write to OutP (final output projection)
// ---------------------------------------------------------------------------
__global__ __launch_bounds__(256) void sgemm_bias(
    const float* __restrict__ Ain, const float* __restrict__ W,
    const float* __restrict__ bias, float* __restrict__ OutP, int dst)
{
    __shared__ float As[8][128];   // A transposed: As[k][m]
    __shared__ float Ws[8][128];   // Ws[k][n]

    const int tid = threadIdx.x;
    const int bx  = blockIdx.x;    // N/128
    const int by  = blockIdx.y;    // M/128
    const int tx  = tid & 15;
    const int ty  = tid >> 4;

    float* Out;
    bool   split;
    if      (dst == 0) { Out = g_Q; split = true; }
    else if (dst == 1) { Out = g_K; split = true; }
    else if (dst == 2) { Out = g_V; split = true; }
    else               { Out = OutP; split = false; }
    const float* A = (dst == 3) ? (const float*)g_ctx : Ain;

    float acc[8][8];
    #pragma unroll
    for (int i = 0; i < 8; i++)
        #pragma unroll
        for (int j = 0; j < 8; j++) acc[i][j] = 0.f;

    // A tile load: each thread one float4 -> row = tid/2, cols (tid&1)*4..
    const int arow = tid >> 1;
    const int acol = (tid & 1) * 4;
    // W tile load: row = tid/32, cols (tid&31)*4
    const int wrow = tid >> 5;
    const int wcol = (tid & 31) * 4;

    const float* Aptr = A + (by * 128 + arow) * Dn + acol;
    const float* Wptr = W + wrow * Dn + bx * 128 + wcol;

    for (int k0 = 0; k0 < Dn; k0 += 8) {
        float4 av = *(const float4*)(Aptr + k0);
        float4 wv = *(const float4*)(Wptr + k0 * Dn);
        As[acol + 0][arow] = av.x;
        As[acol + 1][arow] = av.y;
        As[acol + 2][arow] = av.z;
        As[acol + 3][arow] = av.w;
        *(float4*)&Ws[wrow][wcol] = wv;
        __syncthreads();

        #pragma unroll
        for (int k = 0; k < 8; k++) {
            float a[8], b[8];
            *(float4*)(a)     = *(const float4*)&As[k][ty * 8];
            *(float4*)(a + 4) = *(const float4*)&As[k][ty * 8 + 4];
            *(float4*)(b)     = *(const float4*)&Ws[k][tx * 8];
            *(float4*)(b + 4) = *(const float4*)&Ws[k][tx * 8 + 4];
            #pragma unroll
            for (int i = 0; i < 8; i++)
                #pragma unroll
                for (int j = 0; j < 8; j++)
                    acc[i][j] += a[i] * b[j];
        }
        __syncthreads();
    }

    // Epilogue
    #pragma unroll
    for (int i = 0; i < 8; i++) {
        const int m = by * 128 + ty * 8 + i;
        const int b = m >> 11;          // m / Sn
        const int s = m & (Sn - 1);
        #pragma unroll
        for (int j = 0; j < 8; j += 4) {
            const int n = bx * 128 + tx * 8 + j;
            float4 v;
            v.x = acc[i][j + 0] + bias[n + 0];
            v.y = acc[i][j + 1] + bias[n + 1];
            v.z = acc[i][j + 2] + bias[n + 2];
            v.w = acc[i][j + 3] + bias[n + 3];
            if (split) {
                const int h  = n >> 6;
                const int dk = n & 63;
                *(float4*)&Out[((b * Hn + h) * Sn + s) * DKn + dk] = v;
            } else {
                *(float4*)&Out[m * Dn + n] = v;
            }
        }
    }
}

// ---------------------------------------------------------------------------
// Flash attention: one CTA per (b, h, 64-row q tile). 256 threads.
// Online softmax over 32 key tiles of 64. K stored transposed in smem.
// ---------------------------------------------------------------------------
__global__ __launch_bounds__(256) void flash_attn(const int* __restrict__ mask)
{
    extern __shared__ float sm[];
    float* Qs   = sm;                  // [64][LD]  Q (pre-scaled)
    float* KV   = sm + 64 * LD;        // [64][LD]  K^T, then V
    float* Ss   = sm + 2 * 64 * LD;    // [64][LD]  scores -> probabilities
    float* m_sh = sm + 3 * 64 * LD;    // [64] running max
    float* l_sh = m_sh + 64;           // [64] running sum
    float* fsh  = l_sh + 64;           // [64] rescale factor
    float* msk  = fsh + 64;            // [64] mask flags (1 = masked out)

    const int tid = threadIdx.x;
    const int qt  = blockIdx.x;
    const int h   = blockIdx.y;
    const int b   = blockIdx.z;
    const int q0  = qt * 64;

    const float* Qg = g_Q + ((b * Hn + h) * Sn + q0) * DKn;
    const float* Kg = g_K + (b * Hn + h) * Sn * DKn;
    const float* Vg = g_V + (b * Hn + h) * Sn * DKn;

    // Load Q tile, scaled by 1/sqrt(DK) = 0.125
    {
        const int r  = tid >> 2;
        const int c4 = (tid & 3) * 16;
        #pragma unroll
        for (int u = 0; u < 16; u += 4) {
            float4 v = *(const float4*)&Qg[r * DKn + c4 + u];
            v.x *= 0.125f; v.y *= 0.125f; v.z *= 0.125f; v.w *= 0.125f;
            *(float4*)&Qs[r * LD + c4 + u] = v;
        }
    }
    if (tid < 64) { m_sh[tid] = -1e30f; l_sh[tid] = 0.f; }

    const int ty = tid >> 4;
    const int tx = tid & 15;
    float o[4][4];
    #pragma unroll
    for (int i = 0; i < 4; i++)
        #pragma unroll
        for (int j = 0; j < 4; j++) o[i][j] = 0.f;

    for (int kt = 0; kt < Sn / 64; kt++) {
        const int kk0 = kt * 64;

        // Load K^T into KV: KV[d][c] = K[kk0+c][d]
        {
            const int c  = tid >> 2;
            const int d4 = (tid & 3) * 16;
            #pragma unroll
            for (int u = 0; u < 16; u += 4) {
                float4 v = *(const float4*)&Kg[(kk0 + c) * DKn + d4 + u];
                KV[(d4 + u + 0) * LD + c] = v.x;
                KV[(d4 + u + 1) * LD + c] = v.y;
                KV[(d4 + u + 2) * LD + c] = v.z;
                KV[(d4 + u + 3) * LD + c] = v.w;
            }
        }
        if (tid < 64) msk[tid] = (mask[b * Sn + kk0 + tid] == 0) ? 1.f : 0.f;
        __syncthreads();

        // S = Qs @ K^T  (4x4 per thread; rows = queries ty*4+i, cols = keys tx*4+j)
        {
            float sc[4][4];
            #pragma unroll
            for (int i = 0; i < 4; i++)
                #pragma unroll
                for (int j = 0; j < 4; j++) sc[i][j] = 0.f;

            #pragma unroll 4
            for (int k = 0; k < 64; k++) {
                const float a0 = Qs[(ty * 4 + 0) * LD + k];
                const float a1 = Qs[(ty * 4 + 1) * LD + k];
                const float a2 = Qs[(ty * 4 + 2) * LD + k];
                const float a3 = Qs[(ty * 4 + 3) * LD + k];
                const float* bp = &KV[k * LD + tx * 4];
                const float b0 = bp[0], b1 = bp[1], b2 = bp[2], b3 = bp[3];
                sc[0][0] += a0 * b0; sc[0][1] += a0 * b1; sc[0][2] += a0 * b2; sc[0][3] += a0 * b3;
                sc[1][0] += a1 * b0; sc[1][1] += a1 * b1; sc[1][2] += a1 * b2; sc[1][3] += a1 * b3;
                sc[2][0] += a2 * b0; sc[2][1] += a2 * b1; sc[2][2] += a2 * b2; sc[2][3] += a2 * b3;
                sc[3][0] += a3 * b0; sc[3][1] += a3 * b1; sc[3][2] += a3 * b2; sc[3][3] += a3 * b3;
            }
            #pragma unroll
            for (int i = 0; i < 4; i++)
                #pragma unroll
                for (int j = 0; j < 4; j++) {
                    float s = sc[i][j];
                    if (msk[tx * 4 + j] != 0.f) s = -1e30f;
                    Ss[(ty * 4 + i) * LD + tx * 4 + j] = s;
                }
        }
        __syncthreads();

        // Load V into KV (overwrites K^T) — overlaps with softmax below
        {
            const int r  = tid >> 2;
            const int c4 = (tid & 3) * 16;
            #pragma unroll
            for (int u = 0; u < 16; u += 4)
                *(float4*)&KV[r * LD + c4 + u] =
                    *(const float4*)&Vg[(kk0 + r) * DKn + c4 + u];
        }

        // Online softmax: 4 threads per row, 16 cols each
        {
            const int row  = tid >> 2;
            const int part = tid & 3;
            float vals[16];
            float mloc = -1e30f;
            #pragma unroll
            for (int j = 0; j < 16; j++) {
                vals[j] = Ss[row * LD + part * 16 + j];
                mloc = fmaxf(mloc, vals[j]);
            }
            mloc = fmaxf(mloc, __shfl_xor_sync(0xffffffffu, mloc, 1));
            mloc = fmaxf(mloc, __shfl_xor_sync(0xffffffffu, mloc, 2));
            const float mold = m_sh[row];
            const float mnew = fmaxf(mold, mloc);
            float ssum = 0.f;
            #pragma unroll
            for (int j = 0; j < 16; j++) {
                const float p = (vals[j] <= -1e29f) ? 0.f : __expf(vals[j] - mnew);
                Ss[row * LD + part * 16 + j] = p;
                ssum += p;
            }
            ssum += __shfl_xor_sync(0xffffffffu, ssum, 1);
            ssum += __shfl_xor_sync(0xffffffffu, ssum, 2);
            if (part == 0) {
                const float f = __expf(mold - mnew);   // mold=-1e30 -> 0 (no NaN)
                l_sh[row] = l_sh[row] * f + ssum;
                m_sh[row] = mnew;
                fsh[row]  = f;
            }
        }
        __syncthreads();

        // Rescale O, then O += P @ V
        #pragma unroll
        for (int i = 0; i < 4; i++) {
            const float f = fsh[ty * 4 + i];
            #pragma unroll
            for (int j = 0; j < 4; j++) o[i][j] *= f;
        }
        #pragma unroll 4
        for (int k = 0; k < 64; k++) {
            const float a0 = Ss[(ty * 4 + 0) * LD + k];
            const float a1 = Ss[(ty * 4 + 1) * LD + k];
            const float a2 = Ss[(ty * 4 + 2) * LD + k];
            const float a3 = Ss[(ty * 4 + 3) * LD + k];
            const float* bp = &KV[k * LD + tx * 4];
            const float b0 = bp[0], b1 = bp[1], b2 = bp[2], b3 = bp[3];
            o[0][0] += a0 * b0; o[0][1] += a0 * b1; o[0][2] += a0 * b2; o[0][3] += a0 * b3;
            o[1][0] += a1 * b0; o[1][1] += a1 * b1; o[1][2] += a1 * b2; o[1][3] += a1 * b3;
            o[2][0] += a2 * b0; o[2][1] += a2 * b1; o[2][2] += a2 * b2; o[2][3] += a2 * b3;
            o[3][0] += a3 * b0; o[3][1] += a3 * b1; o[3][2] += a3 * b2; o[3][3] += a3 * b3;
        }
        __syncthreads();
    }

    // Normalize and write ctx in (B,S,D) layout for the output projection
    #pragma unroll
    for (int i = 0; i < 4; i++) {
        const int r = ty * 4 + i;
        const float inv = 1.f / l_sh[r];
        float4 v;
        v.x = o[i][0] * inv; v.y = o[i][1] * inv;
        v.z = o[i][2] * inv; v.w = o[i][3] * inv;
        *(float4*)&g_ctx[(b * Sn + q0 + r) * Dn + h * DKn + tx * 4] = v;
    }
}

// ---------------------------------------------------------------------------
extern "C" void kernel_launch(void* const* d_in, const int* in_sizes, int n_in,
                              void* d_out, int out_size)
{
    const float* q    = (const float*)d_in[0];
    const float* k    = (const float*)d_in[1];
    const float* v    = (const float*)d_in[2];
    const int*   mask = (const int*)  d_in[3];
    const float* Wq   = (const float*)d_in[4];
    const float* bq   = (const float*)d_in[5];
    const float* Wk   = (const float*)d_in[6];
    const float* bk   = (const float*)d_in[7];
    const float* Wv   = (const float*)d_in[8];
    const float* bv   = (const float*)d_in[9];
    const float* Wo   = (const float*)d_in[10];
    const float* bo   = (const float*)d_in[11];
    float* out = (float*)d_out;

    const dim3 gg(Dn / 128, Mn / 128);
    sgemm_bias<<<gg, 256>>>(q, Wq, bq, nullptr, 0);
    sgemm_bias<<<gg, 256>>>(k, Wk, bk, nullptr, 1);
    sgemm_bias<<<gg, 256>>>(v, Wv, bv, nullptr, 2);

    const int smem = (3 * 64 * LD + 4 * 64) * (int)sizeof(float);  // 53248 B
    (void)cudaFuncSetAttribute(flash_attn, cudaFuncAttributeMaxDynamicSharedMemorySize, smem);
    const dim3 ga(Sn / 64, Hn, Bn);
    flash_attn<<<ga, 256, smem>>>(mask);

    sgemm_bias<<<gg, 256>>>(nullptr, Wo, bo, out, 3);
}

// round 4
// speedup vs baseline: 1.1079x; 1.1079x over previous
#include <cuda_runtime.h>
#include <math.h>
#include <stdint.h>

#define Bn 4
#define Sn 2048
#define Dn 1024
#define Hn 16
#define DKn 64
#define Mn (Bn*Sn)   /* 8192 */
#define LD 68        /* smem row stride for attention tiles */

// Scratch (device globals: allocation-free per harness rules)
__device__ float g_Q[Bn*Hn*Sn*DKn];
__device__ float g_K[Bn*Hn*Sn*DKn];
__device__ float g_V[Bn*Hn*Sn*DKn];
__device__ float g_ctx[Mn*Dn];

__device__ __forceinline__ uint32_t f2tf(float f) {
    uint32_t u;
    asm("cvt.rna.tf32.f32 %0, %1;" : "=r"(u) : "f"(f));
    return u;
}

#define MMA_TF32(c, a, b) asm volatile( \
    "mma.sync.aligned.m16n8k8.row.col.f32.tf32.tf32.f32 " \
    "{%0,%1,%2,%3}, {%4,%5,%6,%7}, {%8,%9}, {%0,%1,%2,%3};\n" \
    : "+f"((c)[0]), "+f"((c)[1]), "+f"((c)[2]), "+f"((c)[3]) \
    : "r"((a)[0]), "r"((a)[1]), "r"((a)[2]), "r"((a)[3]), \
      "r"((b)[0]), "r"((b)[1]))

// ---------------------------------------------------------------------------
// tf32 tensor-core GEMM: C[M,N] = A[M,K] @ W[K,N] + bias. M=8192, N=K=1024.
// BM=BN=128, BK=16, 256 threads (8 warps, 4x2 m-n grid, 32x64 per warp).
// Smem holds operands pre-swizzled into m16n8k8 fragment order (tf32 bits):
//   sA[(mt8*2+kt)*128 + lane*4 + reg]   (8 mtiles x 2 ktiles)
//   sB[(nt16*2+kt)*64 + lane*2 + reg]   (16 ntiles x 2 ktiles)
// dst: 0/1/2 -> g_Q/g_K/g_V head-split write; 3 -> A=g_ctx, plain write.
// ---------------------------------------------------------------------------
__device__ __forceinline__ void storeAfrag(uint32_t* sA, int arow, int k4, float4 v) {
    const int kt  = k4 >> 3;
    const int reg = (((arow & 15) >= 8) ? 1 : 0) | ((k4 & 4) ? 2 : 0);
    const int base = (((arow >> 4) * 2 + kt) << 7) + ((arow & 7) << 4) + reg;
    sA[base + 0]  = f2tf(v.x);
    sA[base + 4]  = f2tf(v.y);
    sA[base + 8]  = f2tf(v.z);
    sA[base + 12] = f2tf(v.w);
}

__device__ __forceinline__ void storeBfrag(uint32_t* sB, int krow, int n4, float4 v) {
    const int kt  = krow >> 3;
    const int reg = ((krow & 7) >= 4) ? 1 : 0;
    const int base = ((n4 >> 3) * 2 + kt) * 64 + ((n4 & 7) * 4 + (krow & 3)) * 2 + reg;
    sB[base + 0]  = f2tf(v.x);
    sB[base + 8]  = f2tf(v.y);
    sB[base + 16] = f2tf(v.z);
    sB[base + 24] = f2tf(v.w);
}

__global__ __launch_bounds__(256) void gemm_tf32(
    const float* __restrict__ Ain, const float* __restrict__ W,
    const float* __restrict__ bias, float* __restrict__ OutP, int dst)
{
    __shared__ uint32_t sA[2048];   // 128 x 16, fragment order
    __shared__ uint32_t sB[2048];   // 16 x 128, fragment order

    const int tid  = threadIdx.x;
    const int bx   = blockIdx.x;    // N/128
    const int by   = blockIdx.y;    // M/128
    const int wid  = tid >> 5;
    const int lane = tid & 31;
    const int wm   = wid & 3;       // m-warp: 32 rows each
    const int wn   = wid >> 2;      // n-warp: 64 cols each
    const int gid  = lane >> 2;
    const int tig  = lane & 3;

    float* Out;
    bool   split;
    if      (dst == 0) { Out = g_Q;  split = true;  }
    else if (dst == 1) { Out = g_K;  split = true;  }
    else if (dst == 2) { Out = g_V;  split = true;  }
    else               { Out = OutP; split = false; }
    const float* A = (dst == 3) ? (const float*)g_ctx : Ain;

    float c[2][8][4];
    #pragma unroll
    for (int mt = 0; mt < 2; mt++)
        #pragma unroll
        for (int nt = 0; nt < 8; nt++)
            #pragma unroll
            for (int r = 0; r < 4; r++) c[mt][nt][r] = 0.f;

    // Loader geometry: A tile 128x16 (row=tid/2, k-group=(tid&1)*8),
    //                  W tile 16x128 (k=tid/16, n-group=(tid&15)*8)
    const int arow  = tid >> 1;
    const int acol8 = (tid & 1) * 8;
    const int brow  = tid >> 4;
    const int bcol8 = (tid & 15) * 8;

    const float* Ap = A + (by * 128 + arow) * Dn + acol8;
    const float* Wp = W + brow * Dn + bx * 128 + bcol8;

    float4 ar0 = *(const float4*)Ap;
    float4 ar1 = *(const float4*)(Ap + 4);
    float4 wr0 = *(const float4*)Wp;
    float4 wr1 = *(const float4*)(Wp + 4);
    Ap += 16; Wp += (size_t)16 * Dn;

    storeAfrag(sA, arow, acol8,     ar0);
    storeAfrag(sA, arow, acol8 + 4, ar1);
    storeBfrag(sB, brow, bcol8,     wr0);
    storeBfrag(sB, brow, bcol8 + 4, wr1);
    __syncthreads();

    for (int it = 1; it <= Dn / 16; it++) {
        const bool more = it < Dn / 16;
        if (more) {
            ar0 = *(const float4*)Ap;
            ar1 = *(const float4*)(Ap + 4);
            wr0 = *(const float4*)Wp;
            wr1 = *(const float4*)(Wp + 4);
            Ap += 16; Wp += (size_t)16 * Dn;
        }

        #pragma unroll
        for (int kt = 0; kt < 2; kt++) {
            uint32_t af[2][4];
            uint32_t bf[8][2];
            #pragma unroll
            for (int mt = 0; mt < 2; mt++)
                *(uint4*)af[mt] =
                    *(const uint4*)&sA[(((wm * 2 + mt) * 2 + kt) << 7) + (lane << 2)];
            #pragma unroll
            for (int nt = 0; nt < 8; nt++)
                *(uint2*)bf[nt] =
                    *(const uint2*)&sB[(((wn * 8 + nt) * 2 + kt) << 6) + (lane << 1)];
            #pragma unroll
            for (int mt = 0; mt < 2; mt++)
                #pragma unroll
                for (int nt = 0; nt < 8; nt++)
                    MMA_TF32(c[mt][nt], af[mt], bf[nt]);
        }

        if (more) {
            __syncthreads();
            storeAfrag(sA, arow, acol8,     ar0);
            storeAfrag(sA, arow, acol8 + 4, ar1);
            storeBfrag(sB, brow, bcol8,     wr0);
            storeBfrag(sB, brow, bcol8 + 4, wr1);
            __syncthreads();
        }
    }

    // Epilogue: bias add, optional head-split store
    #pragma unroll
    for (int mt = 0; mt < 2; mt++) {
        const int m0 = by * 128 + wm * 32 + mt * 16 + gid;
        #pragma unroll
        for (int nt = 0; nt < 8; nt++) {
            const int n = bx * 128 + wn * 64 + nt * 8 + tig * 2;
            const float b0v = bias[n], b1v = bias[n + 1];
            float2 v0 = { c[mt][nt][0] + b0v, c[mt][nt][1] + b1v };
            float2 v1 = { c[mt][nt][2] + b0v, c[mt][nt][3] + b1v };
            if (split) {
                const int h  = n >> 6;
                const int dk = n & 63;
                const int b0i = m0 >> 11, s0 = m0 & (Sn - 1);
                *(float2*)&Out[((b0i * Hn + h) * Sn + s0) * DKn + dk] = v0;
                const int m1 = m0 + 8;
                const int b1i = m1 >> 11, s1 = m1 & (Sn - 1);
                *(float2*)&Out[((b1i * Hn + h) * Sn + s1) * DKn + dk] = v1;
            } else {
                *(float2*)&Out[m0 * Dn + n]       = v0;
                *(float2*)&Out[(m0 + 8) * Dn + n] = v1;
            }
        }
    }
}

// ---------------------------------------------------------------------------
// Flash attention: one CTA per (b, h, 64-row q tile). 256 threads.
// Q stored TRANSPOSED in smem (Qst[d][q]) so QK inner loop is 2x LDS.128.
// ---------------------------------------------------------------------------
__global__ __launch_bounds__(256) void flash_attn(const int* __restrict__ mask)
{
    extern __shared__ float sm[];
    float* Qst  = sm;                  // [64 dims][LD]  Q^T (pre-scaled)
    float* KV   = sm + 64 * LD;        // [64][LD]  K^T, then V
    float* Ss   = sm + 2 * 64 * LD;    // [64][LD]  scores -> probabilities
    float* m_sh = sm + 3 * 64 * LD;    // [64]
    float* l_sh = m_sh + 64;           // [64]
    float* fsh  = l_sh + 64;           // [64]
    float* msk  = fsh + 64;            // [64]

    const int tid = threadIdx.x;
    const int qt  = blockIdx.x;
    const int h   = blockIdx.y;
    const int b   = blockIdx.z;
    const int q0  = qt * 64;

    const float* Qg = g_Q + ((b * Hn + h) * Sn + q0) * DKn;
    const float* Kg = g_K + (b * Hn + h) * Sn * DKn;
    const float* Vg = g_V + (b * Hn + h) * Sn * DKn;

    // Load Q tile TRANSPOSED, scaled by 1/sqrt(DK) = 0.125
    {
        const int qq = tid >> 2;
        const int d4 = (tid & 3) * 16;
        #pragma unroll
        for (int u = 0; u < 16; u += 4) {
            float4 v = *(const float4*)&Qg[qq * DKn + d4 + u];
            Qst[(d4 + u + 0) * LD + qq] = v.x * 0.125f;
            Qst[(d4 + u + 1) * LD + qq] = v.y * 0.125f;
            Qst[(d4 + u + 2) * LD + qq] = v.z * 0.125f;
            Qst[(d4 + u + 3) * LD + qq] = v.w * 0.125f;
        }
    }
    if (tid < 64) { m_sh[tid] = -1e30f; l_sh[tid] = 0.f; }

    const int ty = tid >> 4;
    const int tx = tid & 15;
    float o[4][4];
    #pragma unroll
    for (int i = 0; i < 4; i++)
        #pragma unroll
        for (int j = 0; j < 4; j++) o[i][j] = 0.f;

    for (int kt = 0; kt < Sn / 64; kt++) {
        const int kk0 = kt * 64;

        // Load K^T into KV: KV[d][c] = K[kk0+c][d]
        {
            const int cc = tid >> 2;
            const int d4 = (tid & 3) * 16;
            #pragma unroll
            for (int u = 0; u < 16; u += 4) {
                float4 v = *(const float4*)&Kg[(kk0 + cc) * DKn + d4 + u];
                KV[(d4 + u + 0) * LD + cc] = v.x;
                KV[(d4 + u + 1) * LD + cc] = v.y;
                KV[(d4 + u + 2) * LD + cc] = v.z;
                KV[(d4 + u + 3) * LD + cc] = v.w;
            }
        }
        if (tid < 64) msk[tid] = (mask[b * Sn + kk0 + tid] == 0) ? 1.f : 0.f;
        __syncthreads();

        // S = Q @ K^T : both operands read as float4 per k
        {
            float sc[4][4];
            #pragma unroll
            for (int i = 0; i < 4; i++)
                #pragma unroll
                for (int j = 0; j < 4; j++) sc[i][j] = 0.f;

            #pragma unroll 4
            for (int k = 0; k < 64; k++) {
                const float4 av = *(const float4*)&Qst[k * LD + ty * 4];
                const float4 bv = *(const float4*)&KV[k * LD + tx * 4];
                sc[0][0] += av.x * bv.x; sc[0][1] += av.x * bv.y; sc[0][2] += av.x * bv.z; sc[0][3] += av.x * bv.w;
                sc[1][0] += av.y * bv.x; sc[1][1] += av.y * bv.y; sc[1][2] += av.y * bv.z; sc[1][3] += av.y * bv.w;
                sc[2][0] += av.z * bv.x; sc[2][1] += av.z * bv.y; sc[2][2] += av.z * bv.z; sc[2][3] += av.z * bv.w;
                sc[3][0] += av.w * bv.x; sc[3][1] += av.w * bv.y; sc[3][2] += av.w * bv.z; sc[3][3] += av.w * bv.w;
            }
            #pragma unroll
            for (int i = 0; i < 4; i++)
                #pragma unroll
                for (int j = 0; j < 4; j++) {
                    float s = sc[i][j];
                    if (msk[tx * 4 + j] != 0.f) s = -1e30f;
                    Ss[(ty * 4 + i) * LD + tx * 4 + j] = s;
                }
        }
        __syncthreads();

        // Load V into KV (overwrites K^T)
        {
            const int r  = tid >> 2;
            const int c4 = (tid & 3) * 16;
            #pragma unroll
            for (int u = 0; u < 16; u += 4)
                *(float4*)&KV[r * LD + c4 + u] =
                    *(const float4*)&Vg[(kk0 + r) * DKn + c4 + u];
        }

        // Online softmax: 4 threads per row, 16 cols each
        {
            const int row  = tid >> 2;
            const int part = tid & 3;
            float vals[16];
            float mloc = -1e30f;
            #pragma unroll
            for (int j = 0; j < 16; j++) {
                vals[j] = Ss[row * LD + part * 16 + j];
                mloc = fmaxf(mloc, vals[j]);
            }
            mloc = fmaxf(mloc, __shfl_xor_sync(0xffffffffu, mloc, 1));
            mloc = fmaxf(mloc, __shfl_xor_sync(0xffffffffu, mloc, 2));
            const float mold = m_sh[row];
            const float mnew = fmaxf(mold, mloc);
            float ssum = 0.f;
            #pragma unroll
            for (int j = 0; j < 16; j++) {
                const float p = (vals[j] <= -1e29f) ? 0.f : __expf(vals[j] - mnew);
                Ss[row * LD + part * 16 + j] = p;
                ssum += p;
            }
            ssum += __shfl_xor_sync(0xffffffffu, ssum, 1);
            ssum += __shfl_xor_sync(0xffffffffu, ssum, 2);
            if (part == 0) {
                const float f = __expf(mold - mnew);
                l_sh[row] = l_sh[row] * f + ssum;
                m_sh[row] = mnew;
                fsh[row]  = f;
            }
        }
        __syncthreads();

        // Rescale O, then O += P @ V
        #pragma unroll
        for (int i = 0; i < 4; i++) {
            const float f = fsh[ty * 4 + i];
            #pragma unroll
            for (int j = 0; j < 4; j++) o[i][j] *= f;
        }
        #pragma unroll 4
        for (int k = 0; k < 64; k++) {
            const float a0 = Ss[(ty * 4 + 0) * LD + k];
            const float a1 = Ss[(ty * 4 + 1) * LD + k];
            const float a2 = Ss[(ty * 4 + 2) * LD + k];
            const float a3 = Ss[(ty * 4 + 3) * LD + k];
            const float4 bv = *(const float4*)&KV[k * LD + tx * 4];
            o[0][0] += a0 * bv.x; o[0][1] += a0 * bv.y; o[0][2] += a0 * bv.z; o[0][3] += a0 * bv.w;
            o[1][0] += a1 * bv.x; o[1][1] += a1 * bv.y; o[1][2] += a1 * bv.z; o[1][3] += a1 * bv.w;
            o[2][0] += a2 * bv.x; o[2][1] += a2 * bv.y; o[2][2] += a2 * bv.z; o[2][3] += a2 * bv.w;
            o[3][0] += a3 * bv.x; o[3][1] += a3 * bv.y; o[3][2] += a3 * bv.z; o[3][3] += a3 * bv.w;
        }
        __syncthreads();
    }

    // Normalize and write ctx in (B,S,D) layout
    #pragma unroll
    for (int i = 0; i < 4; i++) {
        const int r = ty * 4 + i;
        const float inv = 1.f / l_sh[r];
        float4 v;
        v.x = o[i][0] * inv; v.y = o[i][1] * inv;
        v.z = o[i][2] * inv; v.w = o[i][3] * inv;
        *(float4*)&g_ctx[(b * Sn + q0 + r) * Dn + h * DKn + tx * 4] = v;
    }
}

// ---------------------------------------------------------------------------
extern "C" void kernel_launch(void* const* d_in, const int* in_sizes, int n_in,
                              void* d_out, int out_size)
{
    const float* q    = (const float*)d_in[0];
    const float* k    = (const float*)d_in[1];
    const float* v    = (const float*)d_in[2];
    const int*   mask = (const int*)  d_in[3];
    const float* Wq   = (const float*)d_in[4];
    const float* bq   = (const float*)d_in[5];
    const float* Wk   = (const float*)d_in[6];
    const float* bk   = (const float*)d_in[7];
    const float* Wv   = (const float*)d_in[8];
    const float* bv   = (const float*)d_in[9];
    const float* Wo   = (const float*)d_in[10];
    const float* bo   = (const float*)d_in[11];
    float* out = (float*)d_out;

    const dim3 gg(Dn / 128, Mn / 128);
    gemm_tf32<<<gg, 256>>>(q, Wq, bq, nullptr, 0);
    gemm_tf32<<<gg, 256>>>(k, Wk, bk, nullptr, 1);
    gemm_tf32<<<gg, 256>>>(v, Wv, bv, nullptr, 2);

    const int smem = (3 * 64 * LD + 4 * 64) * (int)sizeof(float);  // 53248 B
    (void)cudaFuncSetAttribute(flash_attn, cudaFuncAttributeMaxDynamicSharedMemorySize, smem);
    const dim3 ga(Sn / 64, Hn, Bn);
    flash_attn<<<ga, 256, smem>>>(mask);

    gemm_tf32<<<gg, 256>>>(nullptr, Wo, bo, out, 3);
}

// round 6
// speedup vs baseline: 1.5208x; 1.3727x over previous
#include <cuda_runtime.h>
#include <math.h>
#include <stdint.h>

#define Bn 4
#define Sn 2048
#define Dn 1024
#define Hn 16
#define DKn 64
#define Mn (Bn*Sn)   /* 8192 */
#define LD 68        /* smem row stride for attention tiles */

// Scratch (device globals: allocation-free per harness rules)
__device__ float g_Q[Bn*Hn*Sn*DKn];
__device__ float g_K[Bn*Hn*Sn*DKn];
__device__ float g_V[Bn*Hn*Sn*DKn];
__device__ float g_ctx[Mn*Dn];

__device__ __forceinline__ uint32_t f2tf(float f) {
    uint32_t u;
    asm("cvt.rna.tf32.f32 %0, %1;" : "=r"(u) : "f"(f));
    return u;
}
__device__ __forceinline__ float tf32r(float f) { return __uint_as_float(f2tf(f)); }

#define MMA_TF32(c, a, b) asm volatile( \
    "mma.sync.aligned.m16n8k8.row.col.f32.tf32.tf32.f32 " \
    "{%0,%1,%2,%3}, {%4,%5,%6,%7}, {%8,%9}, {%0,%1,%2,%3};\n" \
    : "+f"((c)[0]), "+f"((c)[1]), "+f"((c)[2]), "+f"((c)[3]) \
    : "r"((a)[0]), "r"((a)[1]), "r"((a)[2]), "r"((a)[3]), \
      "r"((b)[0]), "r"((b)[1]))

// ---------------------------------------------------------------------------
// tf32 tensor-core GEMM (unchanged, proven in R4): C = A @ W + bias.
// ---------------------------------------------------------------------------
__device__ __forceinline__ void storeAfrag(uint32_t* sA, int arow, int k4, float4 v) {
    const int kt  = k4 >> 3;
    const int reg = (((arow & 15) >= 8) ? 1 : 0) | ((k4 & 4) ? 2 : 0);
    const int base = (((arow >> 4) * 2 + kt) << 7) + ((arow & 7) << 4) + reg;
    sA[base + 0]  = f2tf(v.x);
    sA[base + 4]  = f2tf(v.y);
    sA[base + 8]  = f2tf(v.z);
    sA[base + 12] = f2tf(v.w);
}

__device__ __forceinline__ void storeBfrag(uint32_t* sB, int krow, int n4, float4 v) {
    const int kt  = krow >> 3;
    const int reg = ((krow & 7) >= 4) ? 1 : 0;
    const int base = ((n4 >> 3) * 2 + kt) * 64 + ((n4 & 7) * 4 + (krow & 3)) * 2 + reg;
    sB[base + 0]  = f2tf(v.x);
    sB[base + 8]  = f2tf(v.y);
    sB[base + 16] = f2tf(v.z);
    sB[base + 24] = f2tf(v.w);
}

__global__ __launch_bounds__(256) void gemm_tf32(
    const float* __restrict__ Ain, const float* __restrict__ W,
    const float* __restrict__ bias, float* __restrict__ OutP, int dst)
{
    __shared__ uint32_t sA[2048];   // 128 x 16, fragment order
    __shared__ uint32_t sB[2048];   // 16 x 128, fragment order

    const int tid  = threadIdx.x;
    const int bx   = blockIdx.x;
    const int by   = blockIdx.y;
    const int wid  = tid >> 5;
    const int lane = tid & 31;
    const int wm   = wid & 3;
    const int wn   = wid >> 2;
    const int gid  = lane >> 2;
    const int tig  = lane & 3;

    float* Out;
    bool   split;
    if      (dst == 0) { Out = g_Q;  split = true;  }
    else if (dst == 1) { Out = g_K;  split = true;  }
    else if (dst == 2) { Out = g_V;  split = true;  }
    else               { Out = OutP; split = false; }
    const float* A = (dst == 3) ? (const float*)g_ctx : Ain;

    float c[2][8][4];
    #pragma unroll
    for (int mt = 0; mt < 2; mt++)
        #pragma unroll
        for (int nt = 0; nt < 8; nt++)
            #pragma unroll
            for (int r = 0; r < 4; r++) c[mt][nt][r] = 0.f;

    const int arow  = tid >> 1;
    const int acol8 = (tid & 1) * 8;
    const int brow  = tid >> 4;
    const int bcol8 = (tid & 15) * 8;

    const float* Ap = A + (by * 128 + arow) * Dn + acol8;
    const float* Wp = W + brow * Dn + bx * 128 + bcol8;

    float4 ar0 = *(const float4*)Ap;
    float4 ar1 = *(const float4*)(Ap + 4);
    float4 wr0 = *(const float4*)Wp;
    float4 wr1 = *(const float4*)(Wp + 4);
    Ap += 16; Wp += (size_t)16 * Dn;

    storeAfrag(sA, arow, acol8,     ar0);
    storeAfrag(sA, arow, acol8 + 4, ar1);
    storeBfrag(sB, brow, bcol8,     wr0);
    storeBfrag(sB, brow, bcol8 + 4, wr1);
    __syncthreads();

    for (int it = 1; it <= Dn / 16; it++) {
        const bool more = it < Dn / 16;
        if (more) {
            ar0 = *(const float4*)Ap;
            ar1 = *(const float4*)(Ap + 4);
            wr0 = *(const float4*)Wp;
            wr1 = *(const float4*)(Wp + 4);
            Ap += 16; Wp += (size_t)16 * Dn;
        }

        #pragma unroll
        for (int kt = 0; kt < 2; kt++) {
            uint32_t af[2][4];
            uint32_t bf[8][2];
            #pragma unroll
            for (int mt = 0; mt < 2; mt++)
                *(uint4*)af[mt] =
                    *(const uint4*)&sA[(((wm * 2 + mt) * 2 + kt) << 7) + (lane << 2)];
            #pragma unroll
            for (int nt = 0; nt < 8; nt++)
                *(uint2*)bf[nt] =
                    *(const uint2*)&sB[(((wn * 8 + nt) * 2 + kt) << 6) + (lane << 1)];
            #pragma unroll
            for (int mt = 0; mt < 2; mt++)
                #pragma unroll
                for (int nt = 0; nt < 8; nt++)
                    MMA_TF32(c[mt][nt], af[mt], bf[nt]);
        }

        if (more) {
            __syncthreads();
            storeAfrag(sA, arow, acol8,     ar0);
            storeAfrag(sA, arow, acol8 + 4, ar1);
            storeBfrag(sB, brow, bcol8,     wr0);
            storeBfrag(sB, brow, bcol8 + 4, wr1);
            __syncthreads();
        }
    }

    #pragma unroll
    for (int mt = 0; mt < 2; mt++) {
        const int m0 = by * 128 + wm * 32 + mt * 16 + gid;
        #pragma unroll
        for (int nt = 0; nt < 8; nt++) {
            const int n = bx * 128 + wn * 64 + nt * 8 + tig * 2;
            const float b0v = bias[n], b1v = bias[n + 1];
            float2 v0 = { c[mt][nt][0] + b0v, c[mt][nt][1] + b1v };
            float2 v1 = { c[mt][nt][2] + b0v, c[mt][nt][3] + b1v };
            if (split) {
                const int h  = n >> 6;
                const int dk = n & 63;
                const int b0i = m0 >> 11, s0 = m0 & (Sn - 1);
                *(float2*)&Out[((b0i * Hn + h) * Sn + s0) * DKn + dk] = v0;
                const int m1 = m0 + 8;
                const int b1i = m1 >> 11, s1 = m1 & (Sn - 1);
                *(float2*)&Out[((b1i * Hn + h) * Sn + s1) * DKn + dk] = v1;
            } else {
                *(float2*)&Out[m0 * Dn + n]       = v0;
                *(float2*)&Out[(m0 + 8) * Dn + n] = v1;
            }
        }
    }
}

// ---------------------------------------------------------------------------
// Tensor-core flash attention: one CTA per (b, h, 64-row q tile), 256 thr.
// Both matmuls via mma.m16n8k8 tf32; online softmax in smem (unchanged).
// All tiles row-major LD=68: every fragment LDS is bank-conflict-free.
// Warp wm=wid&3 owns 16 q-rows, wn=wid>>2 owns a 32-col half.
// ---------------------------------------------------------------------------
__global__ __launch_bounds__(256) void flash_attn(const int* __restrict__ mask)
{
    extern __shared__ float sm[];
    float* Qs   = sm;                  // [64][LD] tf32-rounded, pre-scaled
    float* KV   = sm + 64 * LD;        // [64][LD] K (tf32), then V (tf32)
    float* Ss   = sm + 2 * 64 * LD;    // [64][LD] scores fp32 -> probs tf32
    float* m_sh = sm + 3 * 64 * LD;    // [64]
    float* l_sh = m_sh + 64;           // [64]
    float* fsh  = l_sh + 64;           // [64]
    float* msk  = fsh + 64;            // [64]

    const int tid = threadIdx.x;
    const int qt  = blockIdx.x;
    const int h   = blockIdx.y;
    const int b   = blockIdx.z;
    const int q0  = qt * 64;

    const int wid  = tid >> 5;
    const int lane = tid & 31;
    const int wm   = wid & 3;
    const int wn   = wid >> 2;
    const int gid  = lane >> 2;
    const int tig  = lane & 3;
    const int row0 = wm * 16 + gid;    // this thread's first q-row

    const float* Qg = g_Q + ((b * Hn + h) * Sn + q0) * DKn;
    const float* Kg = g_K + (b * Hn + h) * Sn * DKn;
    const float* Vg = g_V + (b * Hn + h) * Sn * DKn;

    // Q tile: scale by 0.125, round to tf32 once
    {
        const int r  = tid >> 2;
        const int c4 = (tid & 3) * 16;
        #pragma unroll
        for (int u = 0; u < 16; u += 4) {
            float4 v = *(const float4*)&Qg[r * DKn + c4 + u];
            Qs[r * LD + c4 + u + 0] = tf32r(v.x * 0.125f);
            Qs[r * LD + c4 + u + 1] = tf32r(v.y * 0.125f);
            Qs[r * LD + c4 + u + 2] = tf32r(v.z * 0.125f);
            Qs[r * LD + c4 + u + 3] = tf32r(v.w * 0.125f);
        }
    }
    if (tid < 64) { m_sh[tid] = -1e30f; l_sh[tid] = 0.f; }

    float o[4][4];
    #pragma unroll
    for (int nt = 0; nt < 4; nt++)
        #pragma unroll
        for (int r = 0; r < 4; r++) o[nt][r] = 0.f;

    for (int kt = 0; kt < Sn / 64; kt++) {
        const int kk0 = kt * 64;

        // K tile (row-major, tf32)
        {
            const int r  = tid >> 2;
            const int c4 = (tid & 3) * 16;
            #pragma unroll
            for (int u = 0; u < 16; u += 4) {
                float4 v = *(const float4*)&Kg[(kk0 + r) * DKn + c4 + u];
                KV[r * LD + c4 + u + 0] = tf32r(v.x);
                KV[r * LD + c4 + u + 1] = tf32r(v.y);
                KV[r * LD + c4 + u + 2] = tf32r(v.z);
                KV[r * LD + c4 + u + 3] = tf32r(v.w);
            }
        }
        if (tid < 64) msk[tid] = (mask[b * Sn + kk0 + tid] == 0) ? 1.f : 0.f;
        __syncthreads();

        // S = Q @ K^T via mma (A = Q row-major, B = K rows as col-major k x n)
        {
            float cs[4][4];
            #pragma unroll
            for (int nt = 0; nt < 4; nt++)
                #pragma unroll
                for (int r = 0; r < 4; r++) cs[nt][r] = 0.f;

            #pragma unroll
            for (int ks = 0; ks < 8; ks++) {
                const int kk = ks * 8;
                uint32_t a[4];
                const float* Ap = &Qs[row0 * LD + kk + tig];
                a[0] = __float_as_uint(Ap[0]);
                a[1] = __float_as_uint(Ap[8 * LD]);
                a[2] = __float_as_uint(Ap[4]);
                a[3] = __float_as_uint(Ap[8 * LD + 4]);
                #pragma unroll
                for (int nt = 0; nt < 4; nt++) {
                    uint32_t bb[2];
                    const float* Bp = &KV[(wn * 32 + nt * 8 + gid) * LD + kk + tig];
                    bb[0] = __float_as_uint(Bp[0]);
                    bb[1] = __float_as_uint(Bp[4]);
                    MMA_TF32(cs[nt], a, bb);
                }
            }
            #pragma unroll
            for (int nt = 0; nt < 4; nt++) {
                const int col = wn * 32 + nt * 8 + tig * 2;
                float2 v0 = { cs[nt][0], cs[nt][1] };
                float2 v1 = { cs[nt][2], cs[nt][3] };
                *(float2*)&Ss[row0 * LD + col]       = v0;
                *(float2*)&Ss[(row0 + 8) * LD + col] = v1;
            }
        }
        __syncthreads();

        // V tile into KV (tf32), overlapped with softmax
        {
            const int r  = tid >> 2;
            const int c4 = (tid & 3) * 16;
            #pragma unroll
            for (int u = 0; u < 16; u += 4) {
                float4 v = *(const float4*)&Vg[(kk0 + r) * DKn + c4 + u];
                KV[r * LD + c4 + u + 0] = tf32r(v.x);
                KV[r * LD + c4 + u + 1] = tf32r(v.y);
                KV[r * LD + c4 + u + 2] = tf32r(v.z);
                KV[r * LD + c4 + u + 3] = tf32r(v.w);
            }
        }

        // Online softmax: 4 threads per row; mask applied at read;
        // probabilities written back tf32-rounded (consistent with l sum).
        {
            const int row  = tid >> 2;
            const int part = tid & 3;
            float vals[16];
            float mloc = -1e30f;
            #pragma unroll
            for (int j = 0; j < 16; j++) {
                float s = Ss[row * LD + part * 16 + j];
                if (msk[part * 16 + j] != 0.f) s = -1e30f;
                vals[j] = s;
                mloc = fmaxf(mloc, s);
            }
            mloc = fmaxf(mloc, __shfl_xor_sync(0xffffffffu, mloc, 1));
            mloc = fmaxf(mloc, __shfl_xor_sync(0xffffffffu, mloc, 2));
            const float mold = m_sh[row];
            const float mnew = fmaxf(mold, mloc);
            float ssum = 0.f;
            #pragma unroll
            for (int j = 0; j < 16; j++) {
                const float p  = (vals[j] <= -1e29f) ? 0.f : __expf(vals[j] - mnew);
                const float pr = tf32r(p);
                Ss[row * LD + part * 16 + j] = pr;
                ssum += pr;
            }
            ssum += __shfl_xor_sync(0xffffffffu, ssum, 1);
            ssum += __shfl_xor_sync(0xffffffffu, ssum, 2);
            if (part == 0) {
                const float f = __expf(mold - mnew);
                l_sh[row] = l_sh[row] * f + ssum;
                m_sh[row] = mnew;
                fsh[row]  = f;
            }
        }
        __syncthreads();

        // Rescale O fragments, then O += P @ V via mma
        {
            const float f0 = fsh[row0];
            const float f1 = fsh[row0 + 8];
            #pragma unroll
            for (int nt = 0; nt < 4; nt++) {
                o[nt][0] *= f0; o[nt][1] *= f0;
                o[nt][2] *= f1; o[nt][3] *= f1;
            }
            #pragma unroll
            for (int ks = 0; ks < 8; ks++) {
                const int kk = ks * 8;
                uint32_t a[4];
                const float* Ap = &Ss[row0 * LD + kk + tig];
                a[0] = __float_as_uint(Ap[0]);
                a[1] = __float_as_uint(Ap[8 * LD]);
                a[2] = __float_as_uint(Ap[4]);
                a[3] = __float_as_uint(Ap[8 * LD + 4]);
                #pragma unroll
                for (int nt = 0; nt < 4; nt++) {
                    uint32_t bb[2];
                    const float* Bp = &KV[(kk + tig) * LD + wn * 32 + nt * 8 + gid];
                    bb[0] = __float_as_uint(Bp[0]);
                    bb[1] = __float_as_uint(Bp[4 * LD]);
                    MMA_TF32(o[nt], a, bb);
                }
            }
        }
        __syncthreads();
    }

    // Normalize and write ctx in (B,S,D) layout
    {
        const float inv0 = 1.f / l_sh[row0];
        const float inv1 = 1.f / l_sh[row0 + 8];
        #pragma unroll
        for (int nt = 0; nt < 4; nt++) {
            const int col = h * DKn + wn * 32 + nt * 8 + tig * 2;
            float2 v0 = { o[nt][0] * inv0, o[nt][1] * inv0 };
            float2 v1 = { o[nt][2] * inv1, o[nt][3] * inv1 };
            *(float2*)&g_ctx[(b * Sn + q0 + row0) * Dn + col]     = v0;
            *(float2*)&g_ctx[(b * Sn + q0 + row0 + 8) * Dn + col] = v1;
        }
    }
}

// ---------------------------------------------------------------------------
extern "C" void kernel_launch(void* const* d_in, const int* in_sizes, int n_in,
                              void* d_out, int out_size)
{
    const float* q    = (const float*)d_in[0];
    const float* k    = (const float*)d_in[1];
    const float* v    = (const float*)d_in[2];
    const int*   mask = (const int*)  d_in[3];
    const float* Wq   = (const float*)d_in[4];
    const float* bq   = (const float*)d_in[5];
    const float* Wk   = (const float*)d_in[6];
    const float* bk   = (const float*)d_in[7];
    const float* Wv   = (const float*)d_in[8];
    const float* bv   = (const float*)d_in[9];
    const float* Wo   = (const float*)d_in[10];
    const float* bo   = (const float*)d_in[11];
    float* out = (float*)d_out;

    const dim3 gg(Dn / 128, Mn / 128);
    gemm_tf32<<<gg, 256>>>(q, Wq, bq, nullptr, 0);
    gemm_tf32<<<gg, 256>>>(k, Wk, bk, nullptr, 1);
    gemm_tf32<<<gg, 256>>>(v, Wv, bv, nullptr, 2);

    const int smem = (3 * 64 * LD + 4 * 64) * (int)sizeof(float);  // 53248 B
    (void)cudaFuncSetAttribute(flash_attn, cudaFuncAttributeMaxDynamicSharedMemorySize, smem);
    const dim3 ga(Sn / 64, Hn, Bn);
    flash_attn<<<ga, 256, smem>>>(mask);

    gemm_tf32<<<gg, 256>>>(nullptr, Wo, bo, out, 3);
}

// round 7
// speedup vs baseline: 1.5881x; 1.0443x over previous
#include <cuda_runtime.h>
#include <math.h>
#include <stdint.h>

#define Bn 4
#define Sn 2048
#define Dn 1024
#define Hn 16
#define DKn 64
#define Mn (Bn*Sn)   /* 8192 */
#define LD 68        /* smem row stride for attention tiles */

// Scratch (device globals: allocation-free per harness rules)
__device__ float g_Q[Bn*Hn*Sn*DKn];
__device__ float g_K[Bn*Hn*Sn*DKn];
__device__ float g_V[Bn*Hn*Sn*DKn];
__device__ float g_ctx[Mn*Dn];

__device__ __forceinline__ uint32_t f2tf(float f) {
    uint32_t u;
    asm("cvt.rna.tf32.f32 %0, %1;" : "=r"(u) : "f"(f));
    return u;
}
__device__ __forceinline__ float tf32r(float f) { return __uint_as_float(f2tf(f)); }

#define MMA_TF32(c, a, b) asm volatile( \
    "mma.sync.aligned.m16n8k8.row.col.f32.tf32.tf32.f32 " \
    "{%0,%1,%2,%3}, {%4,%5,%6,%7}, {%8,%9}, {%0,%1,%2,%3};\n" \
    : "+f"((c)[0]), "+f"((c)[1]), "+f"((c)[2]), "+f"((c)[3]) \
    : "r"((a)[0]), "r"((a)[1]), "r"((a)[2]), "r"((a)[3]), \
      "r"((b)[0]), "r"((b)[1]))

// ---------------------------------------------------------------------------
// tf32 tensor-core GEMM, now DOUBLE-BUFFERED (1 sync per k-step).
// C[M,N] = A[M,K] @ W[K,N] + bias. BM=BN=128, BK=16, 256 threads.
// ---------------------------------------------------------------------------
__device__ __forceinline__ void storeAfrag(uint32_t* sA, int arow, int k4, float4 v) {
    const int kt  = k4 >> 3;
    const int reg = (((arow & 15) >= 8) ? 1 : 0) | ((k4 & 4) ? 2 : 0);
    const int base = (((arow >> 4) * 2 + kt) << 7) + ((arow & 7) << 4) + reg;
    sA[base + 0]  = f2tf(v.x);
    sA[base + 4]  = f2tf(v.y);
    sA[base + 8]  = f2tf(v.z);
    sA[base + 12] = f2tf(v.w);
}

__device__ __forceinline__ void storeBfrag(uint32_t* sB, int krow, int n4, float4 v) {
    const int kt  = krow >> 3;
    const int reg = ((krow & 7) >= 4) ? 1 : 0;
    const int base = ((n4 >> 3) * 2 + kt) * 64 + ((n4 & 7) * 4 + (krow & 3)) * 2 + reg;
    sB[base + 0]  = f2tf(v.x);
    sB[base + 8]  = f2tf(v.y);
    sB[base + 16] = f2tf(v.z);
    sB[base + 24] = f2tf(v.w);
}

__global__ __launch_bounds__(256) void gemm_tf32(
    const float* __restrict__ Ain, const float* __restrict__ W,
    const float* __restrict__ bias, float* __restrict__ OutP, int dst)
{
    __shared__ uint32_t sA[2][2048];   // ping-pong, fragment order
    __shared__ uint32_t sB[2][2048];

    const int tid  = threadIdx.x;
    const int bx   = blockIdx.x;
    const int by   = blockIdx.y;
    const int wid  = tid >> 5;
    const int lane = tid & 31;
    const int wm   = wid & 3;
    const int wn   = wid >> 2;
    const int gid  = lane >> 2;
    const int tig  = lane & 3;

    float* Out;
    bool   split;
    if      (dst == 0) { Out = g_Q;  split = true;  }
    else if (dst == 1) { Out = g_K;  split = true;  }
    else if (dst == 2) { Out = g_V;  split = true;  }
    else               { Out = OutP; split = false; }
    const float* A = (dst == 3) ? (const float*)g_ctx : Ain;

    float c[2][8][4];
    #pragma unroll
    for (int mt = 0; mt < 2; mt++)
        #pragma unroll
        for (int nt = 0; nt < 8; nt++)
            #pragma unroll
            for (int r = 0; r < 4; r++) c[mt][nt][r] = 0.f;

    const int arow  = tid >> 1;
    const int acol8 = (tid & 1) * 8;
    const int brow  = tid >> 4;
    const int bcol8 = (tid & 15) * 8;

    const float* Ap = A + (by * 128 + arow) * Dn + acol8;
    const float* Wp = W + brow * Dn + bx * 128 + bcol8;

    float4 ar0 = *(const float4*)Ap;
    float4 ar1 = *(const float4*)(Ap + 4);
    float4 wr0 = *(const float4*)Wp;
    float4 wr1 = *(const float4*)(Wp + 4);
    Ap += 16; Wp += (size_t)16 * Dn;

    storeAfrag(sA[0], arow, acol8,     ar0);
    storeAfrag(sA[0], arow, acol8 + 4, ar1);
    storeBfrag(sB[0], brow, bcol8,     wr0);
    storeBfrag(sB[0], brow, bcol8 + 4, wr1);
    __syncthreads();

    const int NIT = Dn / 16;
    for (int it = 0; it < NIT; it++) {
        const int  p    = it & 1;
        const bool more = (it + 1 < NIT);
        if (more) {
            ar0 = *(const float4*)Ap;
            ar1 = *(const float4*)(Ap + 4);
            wr0 = *(const float4*)Wp;
            wr1 = *(const float4*)(Wp + 4);
            Ap += 16; Wp += (size_t)16 * Dn;
        }

        #pragma unroll
        for (int kt = 0; kt < 2; kt++) {
            uint32_t af[2][4];
            uint32_t bf[8][2];
            #pragma unroll
            for (int mt = 0; mt < 2; mt++)
                *(uint4*)af[mt] =
                    *(const uint4*)&sA[p][(((wm * 2 + mt) * 2 + kt) << 7) + (lane << 2)];
            #pragma unroll
            for (int nt = 0; nt < 8; nt++)
                *(uint2*)bf[nt] =
                    *(const uint2*)&sB[p][(((wn * 8 + nt) * 2 + kt) << 6) + (lane << 1)];
            #pragma unroll
            for (int mt = 0; mt < 2; mt++)
                #pragma unroll
                for (int nt = 0; nt < 8; nt++)
                    MMA_TF32(c[mt][nt], af[mt], bf[nt]);
        }

        if (more) {
            storeAfrag(sA[p ^ 1], arow, acol8,     ar0);
            storeAfrag(sA[p ^ 1], arow, acol8 + 4, ar1);
            storeBfrag(sB[p ^ 1], brow, bcol8,     wr0);
            storeBfrag(sB[p ^ 1], brow, bcol8 + 4, wr1);
            __syncthreads();
        }
    }

    #pragma unroll
    for (int mt = 0; mt < 2; mt++) {
        const int m0 = by * 128 + wm * 32 + mt * 16 + gid;
        #pragma unroll
        for (int nt = 0; nt < 8; nt++) {
            const int n = bx * 128 + wn * 64 + nt * 8 + tig * 2;
            const float b0v = bias[n], b1v = bias[n + 1];
            float2 v0 = { c[mt][nt][0] + b0v, c[mt][nt][1] + b1v };
            float2 v1 = { c[mt][nt][2] + b0v, c[mt][nt][3] + b1v };
            if (split) {
                const int h  = n >> 6;
                const int dk = n & 63;
                const int b0i = m0 >> 11, s0 = m0 & (Sn - 1);
                *(float2*)&Out[((b0i * Hn + h) * Sn + s0) * DKn + dk] = v0;
                const int m1 = m0 + 8;
                const int b1i = m1 >> 11, s1 = m1 & (Sn - 1);
                *(float2*)&Out[((b1i * Hn + h) * Sn + s1) * DKn + dk] = v1;
            } else {
                *(float2*)&Out[m0 * Dn + n]       = v0;
                *(float2*)&Out[(m0 + 8) * Dn + n] = v1;
            }
        }
    }
}

// ---------------------------------------------------------------------------
// Tensor-core flash attention (as R6) with vectorized tile stores and
// float4 conflict-free softmax r/w.
// ---------------------------------------------------------------------------
__global__ __launch_bounds__(256) void flash_attn(const int* __restrict__ mask)
{
    extern __shared__ float sm[];
    float* Qs   = sm;                  // [64][LD] tf32-rounded, pre-scaled
    float* KV   = sm + 64 * LD;        // [64][LD] K (tf32), then V (tf32)
    float* Ss   = sm + 2 * 64 * LD;    // [64][LD] scores fp32 -> probs tf32
    float* m_sh = sm + 3 * 64 * LD;    // [64]
    float* l_sh = m_sh + 64;           // [64]
    float* fsh  = l_sh + 64;           // [64]
    float* msk  = fsh + 64;            // [64]

    const int tid = threadIdx.x;
    const int qt  = blockIdx.x;
    const int h   = blockIdx.y;
    const int b   = blockIdx.z;
    const int q0  = qt * 64;

    const int wid  = tid >> 5;
    const int lane = tid & 31;
    const int wm   = wid & 3;
    const int wn   = wid >> 2;
    const int gid  = lane >> 2;
    const int tig  = lane & 3;
    const int row0 = wm * 16 + gid;

    const float* Qg = g_Q + ((b * Hn + h) * Sn + q0) * DKn;
    const float* Kg = g_K + (b * Hn + h) * Sn * DKn;
    const float* Vg = g_V + (b * Hn + h) * Sn * DKn;

    // Q tile: scale by 0.125, tf32 round in regs, vector store
    {
        const int r  = tid >> 2;
        const int c4 = (tid & 3) * 16;
        #pragma unroll
        for (int u = 0; u < 16; u += 4) {
            float4 v = *(const float4*)&Qg[r * DKn + c4 + u];
            v.x = tf32r(v.x * 0.125f);
            v.y = tf32r(v.y * 0.125f);
            v.z = tf32r(v.z * 0.125f);
            v.w = tf32r(v.w * 0.125f);
            *(float4*)&Qs[r * LD + c4 + u] = v;
        }
    }
    if (tid < 64) { m_sh[tid] = -1e30f; l_sh[tid] = 0.f; }

    float o[4][4];
    #pragma unroll
    for (int nt = 0; nt < 4; nt++)
        #pragma unroll
        for (int r = 0; r < 4; r++) o[nt][r] = 0.f;

    for (int kt = 0; kt < Sn / 64; kt++) {
        const int kk0 = kt * 64;

        // K tile (row-major, tf32, vector store)
        {
            const int r  = tid >> 2;
            const int c4 = (tid & 3) * 16;
            #pragma unroll
            for (int u = 0; u < 16; u += 4) {
                float4 v = *(const float4*)&Kg[(kk0 + r) * DKn + c4 + u];
                v.x = tf32r(v.x); v.y = tf32r(v.y);
                v.z = tf32r(v.z); v.w = tf32r(v.w);
                *(float4*)&KV[r * LD + c4 + u] = v;
            }
        }
        if (tid < 64) msk[tid] = (mask[b * Sn + kk0 + tid] == 0) ? 1.f : 0.f;
        __syncthreads();

        // S = Q @ K^T via mma
        {
            float cs[4][4];
            #pragma unroll
            for (int nt = 0; nt < 4; nt++)
                #pragma unroll
                for (int r = 0; r < 4; r++) cs[nt][r] = 0.f;

            #pragma unroll
            for (int ks = 0; ks < 8; ks++) {
                const int kk = ks * 8;
                uint32_t a[4];
                const float* Ap = &Qs[row0 * LD + kk + tig];
                a[0] = __float_as_uint(Ap[0]);
                a[1] = __float_as_uint(Ap[8 * LD]);
                a[2] = __float_as_uint(Ap[4]);
                a[3] = __float_as_uint(Ap[8 * LD + 4]);
                #pragma unroll
                for (int nt = 0; nt < 4; nt++) {
                    uint32_t bb[2];
                    const float* Bp = &KV[(wn * 32 + nt * 8 + gid) * LD + kk + tig];
                    bb[0] = __float_as_uint(Bp[0]);
                    bb[1] = __float_as_uint(Bp[4]);
                    MMA_TF32(cs[nt], a, bb);
                }
            }
            #pragma unroll
            for (int nt = 0; nt < 4; nt++) {
                const int col = wn * 32 + nt * 8 + tig * 2;
                float2 v0 = { cs[nt][0], cs[nt][1] };
                float2 v1 = { cs[nt][2], cs[nt][3] };
                *(float2*)&Ss[row0 * LD + col]       = v0;
                *(float2*)&Ss[(row0 + 8) * LD + col] = v1;
            }
        }
        __syncthreads();

        // V tile into KV (tf32, vector store), overlapped with softmax
        {
            const int r  = tid >> 2;
            const int c4 = (tid & 3) * 16;
            #pragma unroll
            for (int u = 0; u < 16; u += 4) {
                float4 v = *(const float4*)&Vg[(kk0 + r) * DKn + c4 + u];
                v.x = tf32r(v.x); v.y = tf32r(v.y);
                v.z = tf32r(v.z); v.w = tf32r(v.w);
                *(float4*)&KV[r * LD + c4 + u] = v;
            }
        }

        // Online softmax: 4 threads/row, float4 vectorized, conflict-free
        {
            const int row  = tid >> 2;
            const int part = tid & 3;
            float4 vv[4], mm[4];
            #pragma unroll
            for (int j4 = 0; j4 < 4; j4++) {
                vv[j4] = *(const float4*)&Ss[row * LD + part * 16 + j4 * 4];
                mm[j4] = *(const float4*)&msk[part * 16 + j4 * 4];
            }
            float mloc = -1e30f;
            #pragma unroll
            for (int j4 = 0; j4 < 4; j4++) {
                vv[j4].x = (mm[j4].x != 0.f) ? -1e30f : vv[j4].x;
                vv[j4].y = (mm[j4].y != 0.f) ? -1e30f : vv[j4].y;
                vv[j4].z = (mm[j4].z != 0.f) ? -1e30f : vv[j4].z;
                vv[j4].w = (mm[j4].w != 0.f) ? -1e30f : vv[j4].w;
                mloc = fmaxf(mloc, fmaxf(fmaxf(vv[j4].x, vv[j4].y),
                                         fmaxf(vv[j4].z, vv[j4].w)));
            }
            mloc = fmaxf(mloc, __shfl_xor_sync(0xffffffffu, mloc, 1));
            mloc = fmaxf(mloc, __shfl_xor_sync(0xffffffffu, mloc, 2));
            const float mold = m_sh[row];
            const float mnew = fmaxf(mold, mloc);
            float ssum = 0.f;
            #pragma unroll
            for (int j4 = 0; j4 < 4; j4++) {
                float4 p;
                p.x = (vv[j4].x <= -1e29f) ? 0.f : tf32r(__expf(vv[j4].x - mnew));
                p.y = (vv[j4].y <= -1e29f) ? 0.f : tf32r(__expf(vv[j4].y - mnew));
                p.z = (vv[j4].z <= -1e29f) ? 0.f : tf32r(__expf(vv[j4].z - mnew));
                p.w = (vv[j4].w <= -1e29f) ? 0.f : tf32r(__expf(vv[j4].w - mnew));
                *(float4*)&Ss[row * LD + part * 16 + j4 * 4] = p;
                ssum += (p.x + p.y) + (p.z + p.w);
            }
            ssum += __shfl_xor_sync(0xffffffffu, ssum, 1);
            ssum += __shfl_xor_sync(0xffffffffu, ssum, 2);
            if (part == 0) {
                const float f = __expf(mold - mnew);
                l_sh[row] = l_sh[row] * f + ssum;
                m_sh[row] = mnew;
                fsh[row]  = f;
            }
        }
        __syncthreads();

        // Rescale O fragments, then O += P @ V via mma
        {
            const float f0 = fsh[row0];
            const float f1 = fsh[row0 + 8];
            #pragma unroll
            for (int nt = 0; nt < 4; nt++) {
                o[nt][0] *= f0; o[nt][1] *= f0;
                o[nt][2] *= f1; o[nt][3] *= f1;
            }
            #pragma unroll
            for (int ks = 0; ks < 8; ks++) {
                const int kk = ks * 8;
                uint32_t a[4];
                const float* Ap = &Ss[row0 * LD + kk + tig];
                a[0] = __float_as_uint(Ap[0]);
                a[1] = __float_as_uint(Ap[8 * LD]);
                a[2] = __float_as_uint(Ap[4]);
                a[3] = __float_as_uint(Ap[8 * LD + 4]);
                #pragma unroll
                for (int nt = 0; nt < 4; nt++) {
                    uint32_t bb[2];
                    const float* Bp = &KV[(kk + tig) * LD + wn * 32 + nt * 8 + gid];
                    bb[0] = __float_as_uint(Bp[0]);
                    bb[1] = __float_as_uint(Bp[4 * LD]);
                    MMA_TF32(o[nt], a, bb);
                }
            }
        }
        __syncthreads();
    }

    // Normalize and write ctx in (B,S,D) layout
    {
        const float inv0 = 1.f / l_sh[row0];
        const float inv1 = 1.f / l_sh[row0 + 8];
        #pragma unroll
        for (int nt = 0; nt < 4; nt++) {
            const int col = h * DKn + wn * 32 + nt * 8 + tig * 2;
            float2 v0 = { o[nt][0] * inv0, o[nt][1] * inv0 };
            float2 v1 = { o[nt][2] * inv1, o[nt][3] * inv1 };
            *(float2*)&g_ctx[(b * Sn + q0 + row0) * Dn + col]     = v0;
            *(float2*)&g_ctx[(b * Sn + q0 + row0 + 8) * Dn + col] = v1;
        }
    }
}

// ---------------------------------------------------------------------------
extern "C" void kernel_launch(void* const* d_in, const int* in_sizes, int n_in,
                              void* d_out, int out_size)
{
    const float* q    = (const float*)d_in[0];
    const float* k    = (const float*)d_in[1];
    const float* v    = (const float*)d_in[2];
    const int*   mask = (const int*)  d_in[3];
    const float* Wq   = (const float*)d_in[4];
    const float* bq   = (const float*)d_in[5];
    const float* Wk   = (const float*)d_in[6];
    const float* bk   = (const float*)d_in[7];
    const float* Wv   = (const float*)d_in[8];
    const float* bv   = (const float*)d_in[9];
    const float* Wo   = (const float*)d_in[10];
    const float* bo   = (const float*)d_in[11];
    float* out = (float*)d_out;

    const dim3 gg(Dn / 128, Mn / 128);
    gemm_tf32<<<gg, 256>>>(q, Wq, bq, nullptr, 0);
    gemm_tf32<<<gg, 256>>>(k, Wk, bk, nullptr, 1);
    gemm_tf32<<<gg, 256>>>(v, Wv, bv, nullptr, 2);

    const int smem = (3 * 64 * LD + 4 * 64) * (int)sizeof(float);  // 53248 B
    (void)cudaFuncSetAttribute(flash_attn, cudaFuncAttributeMaxDynamicSharedMemorySize, smem);
    const dim3 ga(Sn / 64, Hn, Bn);
    flash_attn<<<ga, 256, smem>>>(mask);

    gemm_tf32<<<gg, 256>>>(nullptr, Wo, bo, out, 3);
}

// round 8
// speedup vs baseline: 2.2205x; 1.3982x over previous
#include <cuda_runtime.h>
#include <math.h>
#include <stdint.h>

#define Bn 4
#define Sn 2048
#define Dn 1024
#define Hn 16
#define DKn 64
#define Mn (Bn*Sn)   /* 8192 */
#define LD 68        /* smem row stride: Q/K/S tiles (row-pattern conflict-free) */
#define LDV 72       /* smem row stride: V tile (column-pattern conflict-free)   */

// Scratch (device globals: allocation-free per harness rules)
__device__ float g_Q[Bn*Hn*Sn*DKn];
__device__ float g_K[Bn*Hn*Sn*DKn];
__device__ float g_V[Bn*Hn*Sn*DKn];
__device__ float g_ctx[Mn*Dn];

__device__ __forceinline__ uint32_t f2tf(float f) {
    uint32_t u;
    asm("cvt.rna.tf32.f32 %0, %1;" : "=r"(u) : "f"(f));
    return u;
}
__device__ __forceinline__ float tf32r(float f) { return __uint_as_float(f2tf(f)); }

#define MMA_TF32(c, a, b) asm volatile( \
    "mma.sync.aligned.m16n8k8.row.col.f32.tf32.tf32.f32 " \
    "{%0,%1,%2,%3}, {%4,%5,%6,%7}, {%8,%9}, {%0,%1,%2,%3};\n" \
    : "+f"((c)[0]), "+f"((c)[1]), "+f"((c)[2]), "+f"((c)[3]) \
    : "r"((a)[0]), "r"((a)[1]), "r"((a)[2]), "r"((a)[3]), \
      "r"((b)[0]), "r"((b)[1]))

// ---------------------------------------------------------------------------
// tf32 tensor-core GEMM, double-buffered, with XOR-swizzled fragment layout
// to kill the scatter-store bank conflicts (A was 8-way, B was 16-way).
// C[M,N] = A[M,K] @ W[K,N] + bias. BM=BN=128, BK=16, 256 threads.
// ---------------------------------------------------------------------------
__device__ __forceinline__ void storeAfrag(uint32_t* sA, int arow, int k4, float4 v) {
    const int kt  = k4 >> 3;
    const int reg = (((arow & 15) >= 8) ? 1 : 0) | ((k4 & 4) ? 2 : 0);
    const int a7  = arow & 7;
    const int swz = ((a7 >> 1) & 3) << 2;          // XOR on j-bits [2:4)
    const int base = (((arow >> 4) * 2 + kt) << 7) + (a7 << 4) + reg;
    sA[(base + 0)  ^ swz] = f2tf(v.x);
    sA[(base + 4)  ^ swz] = f2tf(v.y);
    sA[(base + 8)  ^ swz] = f2tf(v.z);
    sA[(base + 12) ^ swz] = f2tf(v.w);
}

__device__ __forceinline__ void storeBfrag(uint32_t* sB, int krow, int n4, float4 v) {
    const int kt    = krow >> 3;
    const int reg   = ((krow & 7) >= 4) ? 1 : 0;
    const int ntile = (n4 >> 3) * 2 + kt;
    const int swz   = ((ntile & 3) << 1) | (((ntile >> 2) & 3) << 3); // bits [1:5)
    const int base  = ntile * 64 + (n4 & 7) * 8 + (krow & 3) * 2 + reg;
    sB[(base + 0)  ^ swz] = f2tf(v.x);
    sB[(base + 8)  ^ swz] = f2tf(v.y);
    sB[(base + 16) ^ swz] = f2tf(v.z);
    sB[(base + 24) ^ swz] = f2tf(v.w);
}

__global__ __launch_bounds__(256) void gemm_tf32(
    const float* __restrict__ Ain, const float* __restrict__ W,
    const float* __restrict__ bias, float* __restrict__ OutP, int dst)
{
    __shared__ uint32_t sA[2][2048];   // ping-pong, swizzled fragment order
    __shared__ uint32_t sB[2][2048];

    const int tid  = threadIdx.x;
    const int bx   = blockIdx.x;
    const int by   = blockIdx.y;
    const int wid  = tid >> 5;
    const int lane = tid & 31;
    const int wm   = wid & 3;
    const int wn   = wid >> 2;
    const int gid  = lane >> 2;
    const int tig  = lane & 3;
    // compute-side swizzled A offset (mirrors storeAfrag's XOR; per-lane,
    // permutes 16B blocks -> stays conflict-free)
    const int la   = (lane << 2) ^ (((lane >> 3) & 3) << 2);

    float* Out;
    bool   split;
    if      (dst == 0) { Out = g_Q;  split = true;  }
    else if (dst == 1) { Out = g_K;  split = true;  }
    else if (dst == 2) { Out = g_V;  split = true;  }
    else               { Out = OutP; split = false; }
    const float* A = (dst == 3) ? (const float*)g_ctx : Ain;

    float c[2][8][4];
    #pragma unroll
    for (int mt = 0; mt < 2; mt++)
        #pragma unroll
        for (int nt = 0; nt < 8; nt++)
            #pragma unroll
            for (int r = 0; r < 4; r++) c[mt][nt][r] = 0.f;

    const int arow  = tid >> 1;
    const int acol8 = (tid & 1) * 8;
    const int brow  = tid >> 4;
    const int bcol8 = (tid & 15) * 8;

    const float* Ap = A + (by * 128 + arow) * Dn + acol8;
    const float* Wp = W + brow * Dn + bx * 128 + bcol8;

    float4 ar0 = *(const float4*)Ap;
    float4 ar1 = *(const float4*)(Ap + 4);
    float4 wr0 = *(const float4*)Wp;
    float4 wr1 = *(const float4*)(Wp + 4);
    Ap += 16; Wp += (size_t)16 * Dn;

    storeAfrag(sA[0], arow, acol8,     ar0);
    storeAfrag(sA[0], arow, acol8 + 4, ar1);
    storeBfrag(sB[0], brow, bcol8,     wr0);
    storeBfrag(sB[0], brow, bcol8 + 4, wr1);
    __syncthreads();

    const int NIT = Dn / 16;
    for (int it = 0; it < NIT; it++) {
        const int  p    = it & 1;
        const bool more = (it + 1 < NIT);
        if (more) {
            ar0 = *(const float4*)Ap;
            ar1 = *(const float4*)(Ap + 4);
            wr0 = *(const float4*)Wp;
            wr1 = *(const float4*)(Wp + 4);
            Ap += 16; Wp += (size_t)16 * Dn;
        }

        #pragma unroll
        for (int kt = 0; kt < 2; kt++) {
            uint32_t af[2][4];
            uint32_t bf[8][2];
            #pragma unroll
            for (int mt = 0; mt < 2; mt++)
                *(uint4*)af[mt] =
                    *(const uint4*)&sA[p][(((wm * 2 + mt) * 2 + kt) << 7) + la];
            #pragma unroll
            for (int nt = 0; nt < 8; nt++) {
                const int ntile = (wn * 8 + nt) * 2 + kt;
                const int swz   = ((ntile & 3) << 1) | (((ntile >> 2) & 3) << 3);
                *(uint2*)bf[nt] =
                    *(const uint2*)&sB[p][ntile * 64 + ((lane << 1) ^ swz)];
            }
            #pragma unroll
            for (int mt = 0; mt < 2; mt++)
                #pragma unroll
                for (int nt = 0; nt < 8; nt++)
                    MMA_TF32(c[mt][nt], af[mt], bf[nt]);
        }

        if (more) {
            storeAfrag(sA[p ^ 1], arow, acol8,     ar0);
            storeAfrag(sA[p ^ 1], arow, acol8 + 4, ar1);
            storeBfrag(sB[p ^ 1], brow, bcol8,     wr0);
            storeBfrag(sB[p ^ 1], brow, bcol8 + 4, wr1);
            __syncthreads();
        }
    }

    #pragma unroll
    for (int mt = 0; mt < 2; mt++) {
        const int m0 = by * 128 + wm * 32 + mt * 16 + gid;
        #pragma unroll
        for (int nt = 0; nt < 8; nt++) {
            const int n = bx * 128 + wn * 64 + nt * 8 + tig * 2;
            const float b0v = bias[n], b1v = bias[n + 1];
            float2 v0 = { c[mt][nt][0] + b0v, c[mt][nt][1] + b1v };
            float2 v1 = { c[mt][nt][2] + b0v, c[mt][nt][3] + b1v };
            if (split) {
                const int h  = n >> 6;
                const int dk = n & 63;
                const int b0i = m0 >> 11, s0 = m0 & (Sn - 1);
                *(float2*)&Out[((b0i * Hn + h) * Sn + s0) * DKn + dk] = v0;
                const int m1 = m0 + 8;
                const int b1i = m1 >> 11, s1 = m1 & (Sn - 1);
                *(float2*)&Out[((b1i * Hn + h) * Sn + s1) * DKn + dk] = v1;
            } else {
                *(float2*)&Out[m0 * Dn + n]       = v0;
                *(float2*)&Out[(m0 + 8) * Dn + n] = v1;
            }
        }
    }
}

// ---------------------------------------------------------------------------
// Tensor-core flash attention. V now in its OWN buffer with LDV=72 so the
// PV column-pattern B-operand reads are conflict-free (bank = 8*tig+gid).
// ---------------------------------------------------------------------------
__global__ __launch_bounds__(256) void flash_attn(const int* __restrict__ mask)
{
    extern __shared__ float sm[];
    float* Qs   = sm;                       // [64][LD]  tf32, pre-scaled
    float* Ks   = sm + 64 * LD;             // [64][LD]  K (tf32)
    float* Ss   = sm + 2 * 64 * LD;         // [64][LD]  scores -> probs
    float* Vs   = sm + 3 * 64 * LD;         // [64][LDV] V (tf32)
    float* m_sh = sm + 3 * 64 * LD + 64 * LDV;
    float* l_sh = m_sh + 64;
    float* fsh  = l_sh + 64;
    float* msk  = fsh + 64;

    const int tid = threadIdx.x;
    const int qt  = blockIdx.x;
    const int h   = blockIdx.y;
    const int b   = blockIdx.z;
    const int q0  = qt * 64;

    const int wid  = tid >> 5;
    const int lane = tid & 31;
    const int wm   = wid & 3;
    const int wn   = wid >> 2;
    const int gid  = lane >> 2;
    const int tig  = lane & 3;
    const int row0 = wm * 16 + gid;

    const float* Qg = g_Q + ((b * Hn + h) * Sn + q0) * DKn;
    const float* Kg = g_K + (b * Hn + h) * Sn * DKn;
    const float* Vg = g_V + (b * Hn + h) * Sn * DKn;

    // Q tile: scale by 0.125, tf32 round in regs, vector store
    {
        const int r  = tid >> 2;
        const int c4 = (tid & 3) * 16;
        #pragma unroll
        for (int u = 0; u < 16; u += 4) {
            float4 v = *(const float4*)&Qg[r * DKn + c4 + u];
            v.x = tf32r(v.x * 0.125f);
            v.y = tf32r(v.y * 0.125f);
            v.z = tf32r(v.z * 0.125f);
            v.w = tf32r(v.w * 0.125f);
            *(float4*)&Qs[r * LD + c4 + u] = v;
        }
    }
    if (tid < 64) { m_sh[tid] = -1e30f; l_sh[tid] = 0.f; }

    float o[4][4];
    #pragma unroll
    for (int nt = 0; nt < 4; nt++)
        #pragma unroll
        for (int r = 0; r < 4; r++) o[nt][r] = 0.f;

    for (int kt = 0; kt < Sn / 64; kt++) {
        const int kk0 = kt * 64;

        // K tile (row-major, tf32, vector store)
        {
            const int r  = tid >> 2;
            const int c4 = (tid & 3) * 16;
            #pragma unroll
            for (int u = 0; u < 16; u += 4) {
                float4 v = *(const float4*)&Kg[(kk0 + r) * DKn + c4 + u];
                v.x = tf32r(v.x); v.y = tf32r(v.y);
                v.z = tf32r(v.z); v.w = tf32r(v.w);
                *(float4*)&Ks[r * LD + c4 + u] = v;
            }
        }
        if (tid < 64) msk[tid] = (mask[b * Sn + kk0 + tid] == 0) ? 1.f : 0.f;
        __syncthreads();

        // S = Q @ K^T via mma
        {
            float cs[4][4];
            #pragma unroll
            for (int nt = 0; nt < 4; nt++)
                #pragma unroll
                for (int r = 0; r < 4; r++) cs[nt][r] = 0.f;

            #pragma unroll
            for (int ks = 0; ks < 8; ks++) {
                const int kk = ks * 8;
                uint32_t a[4];
                const float* Ap = &Qs[row0 * LD + kk + tig];
                a[0] = __float_as_uint(Ap[0]);
                a[1] = __float_as_uint(Ap[8 * LD]);
                a[2] = __float_as_uint(Ap[4]);
                a[3] = __float_as_uint(Ap[8 * LD + 4]);
                #pragma unroll
                for (int nt = 0; nt < 4; nt++) {
                    uint32_t bb[2];
                    const float* Bp = &Ks[(wn * 32 + nt * 8 + gid) * LD + kk + tig];
                    bb[0] = __float_as_uint(Bp[0]);
                    bb[1] = __float_as_uint(Bp[4]);
                    MMA_TF32(cs[nt], a, bb);
                }
            }
            #pragma unroll
            for (int nt = 0; nt < 4; nt++) {
                const int col = wn * 32 + nt * 8 + tig * 2;
                float2 v0 = { cs[nt][0], cs[nt][1] };
                float2 v1 = { cs[nt][2], cs[nt][3] };
                *(float2*)&Ss[row0 * LD + col]       = v0;
                *(float2*)&Ss[(row0 + 8) * LD + col] = v1;
            }
        }
        __syncthreads();

        // V tile into Vs (tf32, LDV stride), overlapped with softmax
        {
            const int r  = tid >> 2;
            const int c4 = (tid & 3) * 16;
            #pragma unroll
            for (int u = 0; u < 16; u += 4) {
                float4 v = *(const float4*)&Vg[(kk0 + r) * DKn + c4 + u];
                v.x = tf32r(v.x); v.y = tf32r(v.y);
                v.z = tf32r(v.z); v.w = tf32r(v.w);
                *(float4*)&Vs[r * LDV + c4 + u] = v;
            }
        }

        // Online softmax: 4 threads/row, float4 vectorized, conflict-free
        {
            const int row  = tid >> 2;
            const int part = tid & 3;
            float4 vv[4], mm[4];
            #pragma unroll
            for (int j4 = 0; j4 < 4; j4++) {
                vv[j4] = *(const float4*)&Ss[row * LD + part * 16 + j4 * 4];
                mm[j4] = *(const float4*)&msk[part * 16 + j4 * 4];
            }
            float mloc = -1e30f;
            #pragma unroll
            for (int j4 = 0; j4 < 4; j4++) {
                vv[j4].x = (mm[j4].x != 0.f) ? -1e30f : vv[j4].x;
                vv[j4].y = (mm[j4].y != 0.f) ? -1e30f : vv[j4].y;
                vv[j4].z = (mm[j4].z != 0.f) ? -1e30f : vv[j4].z;
                vv[j4].w = (mm[j4].w != 0.f) ? -1e30f : vv[j4].w;
                mloc = fmaxf(mloc, fmaxf(fmaxf(vv[j4].x, vv[j4].y),
                                         fmaxf(vv[j4].z, vv[j4].w)));
            }
            mloc = fmaxf(mloc, __shfl_xor_sync(0xffffffffu, mloc, 1));
            mloc = fmaxf(mloc, __shfl_xor_sync(0xffffffffu, mloc, 2));
            const float mold = m_sh[row];
            const float mnew = fmaxf(mold, mloc);
            float ssum = 0.f;
            #pragma unroll
            for (int j4 = 0; j4 < 4; j4++) {
                float4 p;
                p.x = (vv[j4].x <= -1e29f) ? 0.f : tf32r(__expf(vv[j4].x - mnew));
                p.y = (vv[j4].y <= -1e29f) ? 0.f : tf32r(__expf(vv[j4].y - mnew));
                p.z = (vv[j4].z <= -1e29f) ? 0.f : tf32r(__expf(vv[j4].z - mnew));
                p.w = (vv[j4].w <= -1e29f) ? 0.f : tf32r(__expf(vv[j4].w - mnew));
                *(float4*)&Ss[row * LD + part * 16 + j4 * 4] = p;
                ssum += (p.x + p.y) + (p.z + p.w);
            }
            ssum += __shfl_xor_sync(0xffffffffu, ssum, 1);
            ssum += __shfl_xor_sync(0xffffffffu, ssum, 2);
            if (part == 0) {
                const float f = __expf(mold - mnew);
                l_sh[row] = l_sh[row] * f + ssum;
                m_sh[row] = mnew;
                fsh[row]  = f;
            }
        }
        __syncthreads();

        // Rescale O fragments, then O += P @ V via mma (V reads conflict-free)
        {
            const float f0 = fsh[row0];
            const float f1 = fsh[row0 + 8];
            #pragma unroll
            for (int nt = 0; nt < 4; nt++) {
                o[nt][0] *= f0; o[nt][1] *= f0;
                o[nt][2] *= f1; o[nt][3] *= f1;
            }
            #pragma unroll
            for (int ks = 0; ks < 8; ks++) {
                const int kk = ks * 8;
                uint32_t a[4];
                const float* Ap = &Ss[row0 * LD + kk + tig];
                a[0] = __float_as_uint(Ap[0]);
                a[1] = __float_as_uint(Ap[8 * LD]);
                a[2] = __float_as_uint(Ap[4]);
                a[3] = __float_as_uint(Ap[8 * LD + 4]);
                #pragma unroll
                for (int nt = 0; nt < 4; nt++) {
                    uint32_t bb[2];
                    const float* Bp = &Vs[(kk + tig) * LDV + wn * 32 + nt * 8 + gid];
                    bb[0] = __float_as_uint(Bp[0]);
                    bb[1] = __float_as_uint(Bp[4 * LDV]);
                    MMA_TF32(o[nt], a, bb);
                }
            }
        }
        __syncthreads();
    }

    // Normalize and write ctx in (B,S,D) layout
    {
        const float inv0 = 1.f / l_sh[row0];
        const float inv1 = 1.f / l_sh[row0 + 8];
        #pragma unroll
        for (int nt = 0; nt < 4; nt++) {
            const int col = h * DKn + wn * 32 + nt * 8 + tig * 2;
            float2 v0 = { o[nt][0] * inv0, o[nt][1] * inv0 };
            float2 v1 = { o[nt][2] * inv1, o[nt][3] * inv1 };
            *(float2*)&g_ctx[(b * Sn + q0 + row0) * Dn + col]     = v0;
            *(float2*)&g_ctx[(b * Sn + q0 + row0 + 8) * Dn + col] = v1;
        }
    }
}

// ---------------------------------------------------------------------------
extern "C" void kernel_launch(void* const* d_in, const int* in_sizes, int n_in,
                              void* d_out, int out_size)
{
    const float* q    = (const float*)d_in[0];
    const float* k    = (const float*)d_in[1];
    const float* v    = (const float*)d_in[2];
    const int*   mask = (const int*)  d_in[3];
    const float* Wq   = (const float*)d_in[4];
    const float* bq   = (const float*)d_in[5];
    const float* Wk   = (const float*)d_in[6];
    const float* bk   = (const float*)d_in[7];
    const float* Wv   = (const float*)d_in[8];
    const float* bv   = (const float*)d_in[9];
    const float* Wo   = (const float*)d_in[10];
    const float* bo   = (const float*)d_in[11];
    float* out = (float*)d_out;

    const dim3 gg(Dn / 128, Mn / 128);
    gemm_tf32<<<gg, 256>>>(q, Wq, bq, nullptr, 0);
    gemm_tf32<<<gg, 256>>>(k, Wk, bk, nullptr, 1);
    gemm_tf32<<<gg, 256>>>(v, Wv, bv, nullptr, 2);

    const int smem = (3 * 64 * LD + 64 * LDV + 4 * 64) * (int)sizeof(float); // 71680 B
    (void)cudaFuncSetAttribute(flash_attn, cudaFuncAttributeMaxDynamicSharedMemorySize, smem);
    const dim3 ga(Sn / 64, Hn, Bn);
    flash_attn<<<ga, 256, smem>>>(mask);

    gemm_tf32<<<gg, 256>>>(nullptr, Wo, bo, out, 3);
}

// round 9
// speedup vs baseline: 2.8007x; 1.2613x over previous
#include <cuda_runtime.h>
#include <math.h>
#include <stdint.h>

#define Bn 4
#define Sn 2048
#define Dn 1024
#define Hn 16
#define DKn 64
#define Mn (Bn*Sn)   /* 8192 */
#define LD 68        /* smem row stride: Q/K tiles (row-pattern conflict-free) */
#define LDV 72       /* smem row stride: V tile (column-pattern conflict-free) */
#define QT 128       /* q-tile rows per CTA in flash attention */

// Scratch (device globals: allocation-free per harness rules)
__device__ float g_Q[Bn*Hn*Sn*DKn];
__device__ float g_K[Bn*Hn*Sn*DKn];
__device__ float g_V[Bn*Hn*Sn*DKn];
__device__ float g_ctx[Mn*Dn];

__device__ __forceinline__ uint32_t f2tf(float f) {
    uint32_t u;
    asm("cvt.rna.tf32.f32 %0, %1;" : "=r"(u) : "f"(f));
    return u;
}
__device__ __forceinline__ float tf32r(float f) { return __uint_as_float(f2tf(f)); }

#define MMA_TF32(c, a, b) asm volatile( \
    "mma.sync.aligned.m16n8k8.row.col.f32.tf32.tf32.f32 " \
    "{%0,%1,%2,%3}, {%4,%5,%6,%7}, {%8,%9}, {%0,%1,%2,%3};\n" \
    : "+f"((c)[0]), "+f"((c)[1]), "+f"((c)[2]), "+f"((c)[3]) \
    : "r"((a)[0]), "r"((a)[1]), "r"((a)[2]), "r"((a)[3]), \
      "r"((b)[0]), "r"((b)[1]))

// ---------------------------------------------------------------------------
// tf32 tensor-core GEMM (unchanged from R8, proven): double-buffered,
// XOR-swizzled fragment smem. C[M,N] = A[M,K] @ W[K,N] + bias.
// ---------------------------------------------------------------------------
__device__ __forceinline__ void storeAfrag(uint32_t* sA, int arow, int k4, float4 v) {
    const int kt  = k4 >> 3;
    const int reg = (((arow & 15) >= 8) ? 1 : 0) | ((k4 & 4) ? 2 : 0);
    const int a7  = arow & 7;
    const int swz = ((a7 >> 1) & 3) << 2;
    const int base = (((arow >> 4) * 2 + kt) << 7) + (a7 << 4) + reg;
    sA[(base + 0)  ^ swz] = f2tf(v.x);
    sA[(base + 4)  ^ swz] = f2tf(v.y);
    sA[(base + 8)  ^ swz] = f2tf(v.z);
    sA[(base + 12) ^ swz] = f2tf(v.w);
}

__device__ __forceinline__ void storeBfrag(uint32_t* sB, int krow, int n4, float4 v) {
    const int kt    = krow >> 3;
    const int reg   = ((krow & 7) >= 4) ? 1 : 0;
    const int ntile = (n4 >> 3) * 2 + kt;
    const int swz   = ((ntile & 3) << 1) | (((ntile >> 2) & 3) << 3);
    const int base  = ntile * 64 + (n4 & 7) * 8 + (krow & 3) * 2 + reg;
    sB[(base + 0)  ^ swz] = f2tf(v.x);
    sB[(base + 8)  ^ swz] = f2tf(v.y);
    sB[(base + 16) ^ swz] = f2tf(v.z);
    sB[(base + 24) ^ swz] = f2tf(v.w);
}

__global__ __launch_bounds__(256) void gemm_tf32(
    const float* __restrict__ Ain, const float* __restrict__ W,
    const float* __restrict__ bias, float* __restrict__ OutP, int dst)
{
    __shared__ uint32_t sA[2][2048];
    __shared__ uint32_t sB[2][2048];

    const int tid  = threadIdx.x;
    const int bx   = blockIdx.x;
    const int by   = blockIdx.y;
    const int wid  = tid >> 5;
    const int lane = tid & 31;
    const int wm   = wid & 3;
    const int wn   = wid >> 2;
    const int gid  = lane >> 2;
    const int tig  = lane & 3;
    const int la   = (lane << 2) ^ (((lane >> 3) & 3) << 2);

    float* Out;
    bool   split;
    if      (dst == 0) { Out = g_Q;  split = true;  }
    else if (dst == 1) { Out = g_K;  split = true;  }
    else if (dst == 2) { Out = g_V;  split = true;  }
    else               { Out = OutP; split = false; }
    const float* A = (dst == 3) ? (const float*)g_ctx : Ain;

    float c[2][8][4];
    #pragma unroll
    for (int mt = 0; mt < 2; mt++)
        #pragma unroll
        for (int nt = 0; nt < 8; nt++)
            #pragma unroll
            for (int r = 0; r < 4; r++) c[mt][nt][r] = 0.f;

    const int arow  = tid >> 1;
    const int acol8 = (tid & 1) * 8;
    const int brow  = tid >> 4;
    const int bcol8 = (tid & 15) * 8;

    const float* Ap = A + (by * 128 + arow) * Dn + acol8;
    const float* Wp = W + brow * Dn + bx * 128 + bcol8;

    float4 ar0 = *(const float4*)Ap;
    float4 ar1 = *(const float4*)(Ap + 4);
    float4 wr0 = *(const float4*)Wp;
    float4 wr1 = *(const float4*)(Wp + 4);
    Ap += 16; Wp += (size_t)16 * Dn;

    storeAfrag(sA[0], arow, acol8,     ar0);
    storeAfrag(sA[0], arow, acol8 + 4, ar1);
    storeBfrag(sB[0], brow, bcol8,     wr0);
    storeBfrag(sB[0], brow, bcol8 + 4, wr1);
    __syncthreads();

    const int NIT = Dn / 16;
    for (int it = 0; it < NIT; it++) {
        const int  p    = it & 1;
        const bool more = (it + 1 < NIT);
        if (more) {
            ar0 = *(const float4*)Ap;
            ar1 = *(const float4*)(Ap + 4);
            wr0 = *(const float4*)Wp;
            wr1 = *(const float4*)(Wp + 4);
            Ap += 16; Wp += (size_t)16 * Dn;
        }

        #pragma unroll
        for (int kt = 0; kt < 2; kt++) {
            uint32_t af[2][4];
            uint32_t bf[8][2];
            #pragma unroll
            for (int mt = 0; mt < 2; mt++)
                *(uint4*)af[mt] =
                    *(const uint4*)&sA[p][(((wm * 2 + mt) * 2 + kt) << 7) + la];
            #pragma unroll
            for (int nt = 0; nt < 8; nt++) {
                const int ntile = (wn * 8 + nt) * 2 + kt;
                const int swz   = ((ntile & 3) << 1) | (((ntile >> 2) & 3) << 3);
                *(uint2*)bf[nt] =
                    *(const uint2*)&sB[p][ntile * 64 + ((lane << 1) ^ swz)];
            }
            #pragma unroll
            for (int mt = 0; mt < 2; mt++)
                #pragma unroll
                for (int nt = 0; nt < 8; nt++)
                    MMA_TF32(c[mt][nt], af[mt], bf[nt]);
        }

        if (more) {
            storeAfrag(sA[p ^ 1], arow, acol8,     ar0);
            storeAfrag(sA[p ^ 1], arow, acol8 + 4, ar1);
            storeBfrag(sB[p ^ 1], brow, bcol8,     wr0);
            storeBfrag(sB[p ^ 1], brow, bcol8 + 4, wr1);
            __syncthreads();
        }
    }

    #pragma unroll
    for (int mt = 0; mt < 2; mt++) {
        const int m0 = by * 128 + wm * 32 + mt * 16 + gid;
        #pragma unroll
        for (int nt = 0; nt < 8; nt++) {
            const int n = bx * 128 + wn * 64 + nt * 8 + tig * 2;
            const float b0v = bias[n], b1v = bias[n + 1];
            float2 v0 = { c[mt][nt][0] + b0v, c[mt][nt][1] + b1v };
            float2 v1 = { c[mt][nt][2] + b0v, c[mt][nt][3] + b1v };
            if (split) {
                const int h  = n >> 6;
                const int dk = n & 63;
                const int b0i = m0 >> 11, s0 = m0 & (Sn - 1);
                *(float2*)&Out[((b0i * Hn + h) * Sn + s0) * DKn + dk] = v0;
                const int m1 = m0 + 8;
                const int b1i = m1 >> 11, s1 = m1 & (Sn - 1);
                *(float2*)&Out[((b1i * Hn + h) * Sn + s1) * DKn + dk] = v1;
            } else {
                *(float2*)&Out[m0 * Dn + n]       = v0;
                *(float2*)&Out[(m0 + 8) * Dn + n] = v1;
            }
        }
    }
}

// ---------------------------------------------------------------------------
// FA2-style flash attention: CTA = 128 q-rows, 8 warps, each warp owns
// 16 rows x all 64 cols. S/P live in registers; softmax fully in-register
// (shfl over the 4 tig lanes sharing a row); P -> A-frag via shuffles.
// 2 syncthreads per k-tile. Q/K row stride LD=68, V stride LDV=72.
// ---------------------------------------------------------------------------
__global__ __launch_bounds__(256, 2) void flash_attn(const int* __restrict__ mask)
{
    extern __shared__ float sm[];
    float* Qs  = sm;                        // [QT][LD]  Q tf32, pre-scaled
    float* Ks  = sm + QT * LD;              // [64][LD]  K tf32
    float* Vs  = sm + QT * LD + 64 * LD;    // [64][LDV] V tf32
    float* msk = Vs + 64 * LDV;             // [64]

    const int tid = threadIdx.x;
    const int qt  = blockIdx.x;
    const int h   = blockIdx.y;
    const int b   = blockIdx.z;
    const int q0  = qt * QT;

    const int wid  = tid >> 5;
    const int lane = tid & 31;
    const int gid  = lane >> 2;
    const int tig  = lane & 3;
    const int row0 = wid * 16 + gid;        // first of this thread's two rows

    const float* Qg = g_Q + ((b * Hn + h) * Sn + q0) * DKn;
    const float* Kg = g_K + (b * Hn + h) * Sn * DKn;
    const float* Vg = g_V + (b * Hn + h) * Sn * DKn;

    // Q tile: 128 rows, scale 0.125 + tf32 round; each thread one half-row
    {
        const int r   = tid >> 1;
        const int c32 = (tid & 1) * 32;
        #pragma unroll
        for (int u = 0; u < 32; u += 4) {
            float4 v = *(const float4*)&Qg[r * DKn + c32 + u];
            v.x = tf32r(v.x * 0.125f);
            v.y = tf32r(v.y * 0.125f);
            v.z = tf32r(v.z * 0.125f);
            v.w = tf32r(v.w * 0.125f);
            *(float4*)&Qs[r * LD + c32 + u] = v;
        }
    }

    float m0 = -1e30f, m1 = -1e30f, l0 = 0.f, l1 = 0.f;
    float o[8][4];
    #pragma unroll
    for (int nt = 0; nt < 8; nt++)
        #pragma unroll
        for (int r = 0; r < 4; r++) o[nt][r] = 0.f;

    for (int kt = 0; kt < Sn / 64; kt++) {
        const int kk0 = kt * 64;

        // K and V tiles (tf32), mask flags
        {
            const int r  = tid >> 2;
            const int c4 = (tid & 3) * 16;
            #pragma unroll
            for (int u = 0; u < 16; u += 4) {
                float4 v = *(const float4*)&Kg[(kk0 + r) * DKn + c4 + u];
                v.x = tf32r(v.x); v.y = tf32r(v.y);
                v.z = tf32r(v.z); v.w = tf32r(v.w);
                *(float4*)&Ks[r * LD + c4 + u] = v;
            }
            #pragma unroll
            for (int u = 0; u < 16; u += 4) {
                float4 v = *(const float4*)&Vg[(kk0 + r) * DKn + c4 + u];
                v.x = tf32r(v.x); v.y = tf32r(v.y);
                v.z = tf32r(v.z); v.w = tf32r(v.w);
                *(float4*)&Vs[r * LDV + c4 + u] = v;
            }
        }
        if (tid < 64) msk[tid] = (mask[b * Sn + kk0 + tid] == 0) ? 1.f : 0.f;
        __syncthreads();

        // S = Q @ K^T : warp computes its 16 rows x 64 cols (8 n-tiles)
        float s[8][4];
        #pragma unroll
        for (int nt = 0; nt < 8; nt++)
            #pragma unroll
            for (int r = 0; r < 4; r++) s[nt][r] = 0.f;

        #pragma unroll
        for (int ks = 0; ks < 8; ks++) {
            const int kk = ks * 8;
            uint32_t a[4];
            const float* Ap = &Qs[row0 * LD + kk + tig];
            a[0] = __float_as_uint(Ap[0]);
            a[1] = __float_as_uint(Ap[8 * LD]);
            a[2] = __float_as_uint(Ap[4]);
            a[3] = __float_as_uint(Ap[8 * LD + 4]);
            #pragma unroll
            for (int nt = 0; nt < 8; nt++) {
                uint32_t bb[2];
                const float* Bp = &Ks[(nt * 8 + gid) * LD + kk + tig];
                bb[0] = __float_as_uint(Bp[0]);
                bb[1] = __float_as_uint(Bp[4]);
                MMA_TF32(s[nt], a, bb);
            }
        }

        // In-register online softmax. s[nt][0,1]: row gid cols 2tig,2tig+1;
        // s[nt][2,3]: row gid+8 same cols. Mask, row-max over tig lanes.
        float mx0 = -1e30f, mx1 = -1e30f;
        #pragma unroll
        for (int nt = 0; nt < 8; nt++) {
            const float mk0 = msk[nt * 8 + 2 * tig];
            const float mk1 = msk[nt * 8 + 2 * tig + 1];
            if (mk0 != 0.f) { s[nt][0] = -1e30f; s[nt][2] = -1e30f; }
            if (mk1 != 0.f) { s[nt][1] = -1e30f; s[nt][3] = -1e30f; }
            mx0 = fmaxf(mx0, fmaxf(s[nt][0], s[nt][1]));
            mx1 = fmaxf(mx1, fmaxf(s[nt][2], s[nt][3]));
        }
        mx0 = fmaxf(mx0, __shfl_xor_sync(0xffffffffu, mx0, 1));
        mx0 = fmaxf(mx0, __shfl_xor_sync(0xffffffffu, mx0, 2));
        mx1 = fmaxf(mx1, __shfl_xor_sync(0xffffffffu, mx1, 1));
        mx1 = fmaxf(mx1, __shfl_xor_sync(0xffffffffu, mx1, 2));

        const float mn0 = fmaxf(m0, mx0);
        const float mn1 = fmaxf(m1, mx1);
        const float f0  = __expf(m0 - mn0);
        const float f1  = __expf(m1 - mn1);
        m0 = mn0; m1 = mn1;

        float sum0 = 0.f, sum1 = 0.f;
        #pragma unroll
        for (int nt = 0; nt < 8; nt++) {
            float p0 = (s[nt][0] <= -1e29f) ? 0.f : tf32r(__expf(s[nt][0] - mn0));
            float p1 = (s[nt][1] <= -1e29f) ? 0.f : tf32r(__expf(s[nt][1] - mn0));
            float p2 = (s[nt][2] <= -1e29f) ? 0.f : tf32r(__expf(s[nt][2] - mn1));
            float p3 = (s[nt][3] <= -1e29f) ? 0.f : tf32r(__expf(s[nt][3] - mn1));
            s[nt][0] = p0; s[nt][1] = p1; s[nt][2] = p2; s[nt][3] = p3;
            sum0 += p0 + p1;
            sum1 += p2 + p3;
        }
        sum0 += __shfl_xor_sync(0xffffffffu, sum0, 1);
        sum0 += __shfl_xor_sync(0xffffffffu, sum0, 2);
        sum1 += __shfl_xor_sync(0xffffffffu, sum1, 1);
        sum1 += __shfl_xor_sync(0xffffffffu, sum1, 2);
        l0 = l0 * f0 + sum0;
        l1 = l1 * f1 + sum1;

        // Rescale O
        #pragma unroll
        for (int nt = 0; nt < 8; nt++) {
            o[nt][0] *= f0; o[nt][1] *= f0;
            o[nt][2] *= f1; o[nt][3] *= f1;
        }

        // O += P @ V. Convert P C-frags (n-tile ks) to A-frags (k-chunk ks)
        // via shuffles: col j of an 8-tile lives on lane tig=j>>1, elem j&1.
        {
            const int srcA = (lane & ~3) | (tig >> 1);
            const int srcB = srcA + 2;
            const bool odd = (tig & 1) != 0;
            #pragma unroll
            for (int ks = 0; ks < 8; ks++) {
                const float v00 = __shfl_sync(0xffffffffu, s[ks][0], srcA);
                const float v01 = __shfl_sync(0xffffffffu, s[ks][1], srcA);
                const float v02 = __shfl_sync(0xffffffffu, s[ks][2], srcA);
                const float v03 = __shfl_sync(0xffffffffu, s[ks][3], srcA);
                const float v10 = __shfl_sync(0xffffffffu, s[ks][0], srcB);
                const float v11 = __shfl_sync(0xffffffffu, s[ks][1], srcB);
                const float v12 = __shfl_sync(0xffffffffu, s[ks][2], srcB);
                const float v13 = __shfl_sync(0xffffffffu, s[ks][3], srcB);
                uint32_t a[4];
                a[0] = __float_as_uint(odd ? v01 : v00);   // P[gid   ][kk+tig]
                a[1] = __float_as_uint(odd ? v03 : v02);   // P[gid+8 ][kk+tig]
                a[2] = __float_as_uint(odd ? v11 : v10);   // P[gid   ][kk+tig+4]
                a[3] = __float_as_uint(odd ? v13 : v12);   // P[gid+8 ][kk+tig+4]

                const int kk = ks * 8;
                #pragma unroll
                for (int nt = 0; nt < 8; nt++) {
                    uint32_t bb[2];
                    const float* Bp = &Vs[(kk + tig) * LDV + nt * 8 + gid];
                    bb[0] = __float_as_uint(Bp[0]);
                    bb[1] = __float_as_uint(Bp[4 * LDV]);
                    MMA_TF32(o[nt], a, bb);
                }
            }
        }
        __syncthreads();
    }

    // Normalize and write ctx in (B,S,D) layout
    {
        const float inv0 = 1.f / l0;
        const float inv1 = 1.f / l1;
        #pragma unroll
        for (int nt = 0; nt < 8; nt++) {
            const int col = h * DKn + nt * 8 + tig * 2;
            float2 v0 = { o[nt][0] * inv0, o[nt][1] * inv0 };
            float2 v1 = { o[nt][2] * inv1, o[nt][3] * inv1 };
            *(float2*)&g_ctx[(b * Sn + q0 + row0) * Dn + col]     = v0;
            *(float2*)&g_ctx[(b * Sn + q0 + row0 + 8) * Dn + col] = v1;
        }
    }
}

// ---------------------------------------------------------------------------
extern "C" void kernel_launch(void* const* d_in, const int* in_sizes, int n_in,
                              void* d_out, int out_size)
{
    const float* q    = (const float*)d_in[0];
    const float* k    = (const float*)d_in[1];
    const float* v    = (const float*)d_in[2];
    const int*   mask = (const int*)  d_in[3];
    const float* Wq   = (const float*)d_in[4];
    const float* bq   = (const float*)d_in[5];
    const float* Wk   = (const float*)d_in[6];
    const float* bk   = (const float*)d_in[7];
    const float* Wv   = (const float*)d_in[8];
    const float* bv   = (const float*)d_in[9];
    const float* Wo   = (const float*)d_in[10];
    const float* bo   = (const float*)d_in[11];
    float* out = (float*)d_out;

    const dim3 gg(Dn / 128, Mn / 128);
    gemm_tf32<<<gg, 256>>>(q, Wq, bq, nullptr, 0);
    gemm_tf32<<<gg, 256>>>(k, Wk, bk, nullptr, 1);
    gemm_tf32<<<gg, 256>>>(v, Wv, bv, nullptr, 2);

    const int smem = (QT * LD + 64 * LD + 64 * LDV + 64) * (int)sizeof(float); // 70912 B
    (void)cudaFuncSetAttribute(flash_attn, cudaFuncAttributeMaxDynamicSharedMemorySize, smem);
    const dim3 ga(Sn / QT, Hn, Bn);
    flash_attn<<<ga, 256, smem>>>(mask);

    gemm_tf32<<<gg, 256>>>(nullptr, Wo, bo, out, 3);
}